// round 1
// baseline (speedup 1.0000x reference)
#include <cuda_runtime.h>
#include <cuda_bf16.h>
#include <math.h>

#define NN   100000
#define BB   32
#define NPER 3125
#define EE   200000
#define NTOT 100032
#define ETOT 500032
#define ENCNEG ((int)0x807FFFFF)

// ---------------- scratch (static __device__, no allocation) ----------------
__device__ float d_Mv[25 * 128];
__device__ float d_Mt[39 * 128];
__device__ float d_c[128];
__device__ float d_G[128 * 128];
__device__ float d_xh1[NTOT * 128];   // GAT1 projected features
__device__ float d_s1[NTOT * 2];
__device__ float d_d1[NTOT * 2];
__device__ int   d_amax1[NTOT * 2];
__device__ float d_den1[NTOT * 2];
__device__ float d_acc1[NTOT * 128];  // GAT1 numerator accumulator
__device__ float d_xh2[NTOT * 64];
__device__ float d_s2[NTOT];
__device__ float d_d2[NTOT];
__device__ int   d_amax2[NTOT];
__device__ float d_den2[NTOT];
__device__ float d_acc2[BB * 64];

// ---------------- helpers ----------------
__device__ __forceinline__ int enc_f(float f) {
    int i = __float_as_int(f);
    return i >= 0 ? i : (i ^ 0x7FFFFFFF);
}
__device__ __forceinline__ float dec_f(int i) {
    return __int_as_float(i >= 0 ? i : (i ^ 0x7FFFFFFF));
}
__device__ __forceinline__ float lrelu(float x) { return x > 0.f ? x : 0.2f * x; }

__device__ __forceinline__ void edge_sd(int e, const int* __restrict__ ei, int& s, int& d) {
    if (e < EE)               { s = ei[e]; d = ei[EE + e]; }
    else if (e < EE + NN)     { int i = e - EE;         d = i; s = NN + i / NPER; }
    else if (e < EE + 2 * NN) { int i = e - EE - NN;    s = i; d = NN + i / NPER; }
    else                      { int i = e - EE - 2 * NN; s = i; d = i; }
}

// ---------------- kernel: precompute collapsed weights + glb-node features ----------------
__global__ void k_pre(const float* __restrict__ lin_tree_W, const float* __restrict__ lin_tree_b,
                      const float* __restrict__ lin_var_W,  const float* __restrict__ lin_var_b,
                      const float* __restrict__ glb_W,      const float* __restrict__ glb_b,
                      const float* __restrict__ glbNode,    const float* __restrict__ gat1_W,
                      const float* __restrict__ a1s,        const float* __restrict__ a1d)
{
    __shared__ float sbias[64];
    __shared__ float sxg[128];
    __shared__ float sres[4];
    int j = threadIdx.x; // 0..127
    if (j < 64) {
        float acc = glb_b[j];
        for (int k = 0; k < 64; k++)
            acc += lin_var_b[k] * glb_W[k * 64 + j] + lin_tree_b[k] * glb_W[(64 + k) * 64 + j];
        sbias[j] = acc;
    }
    __syncthreads();
    // c[j] = bias_x @ gat1_W
    {
        float cj = 0.f;
        for (int m = 0; m < 64; m++) cj += sbias[m] * gat1_W[m * 128 + j];
        d_c[j] = cj;
    }
    // G = glb_W @ gat1_W  (128x128), column j per thread
    for (int k = 0; k < 128; k++) {
        float a = 0.f;
        for (int m = 0; m < 64; m++) a += glb_W[k * 64 + m] * gat1_W[m * 128 + j];
        d_G[k * 128 + j] = a;
    }
    // Mv = lin_var_W @ G[0:64], Mt = lin_tree_W @ G[64:128]
    for (int i = 0; i < 25; i++) {
        float a = 0.f;
        for (int k = 0; k < 64; k++) a += lin_var_W[i * 64 + k] * d_G[k * 128 + j];
        d_Mv[i * 128 + j] = a;
    }
    for (int i = 0; i < 39; i++) {
        float a = 0.f;
        for (int k = 0; k < 64; k++) a += lin_tree_W[i * 64 + k] * d_G[(64 + k) * 128 + j];
        d_Mt[i * 128 + j] = a;
    }
    // glb node projected features (identical for all 32 glb nodes)
    float xg = 0.f;
    for (int m = 0; m < 64; m++) xg += glbNode[m] * gat1_W[m * 128 + j];
    for (int g = 0; g < BB; g++) d_xh1[(NN + g) * 128 + j] = xg;
    sxg[j] = xg;
    __syncthreads();
    if (j == 0) {
        float s0 = 0, s1 = 0, dd0 = 0, dd1 = 0;
        for (int c = 0; c < 64; c++) {
            s0 += sxg[c] * a1s[c];        dd0 += sxg[c] * a1d[c];
            s1 += sxg[64 + c] * a1s[64 + c]; dd1 += sxg[64 + c] * a1d[64 + c];
        }
        sres[0] = s0; sres[1] = s1; sres[2] = dd0; sres[3] = dd1;
    }
    __syncthreads();
    if (j < BB) {
        d_s1[(NN + j) * 2]     = sres[0];
        d_s1[(NN + j) * 2 + 1] = sres[1];
        d_d1[(NN + j) * 2]     = sres[2];
        d_d1[(NN + j) * 2 + 1] = sres[3];
    }
}

// ---------------- kernel: init accumulators ----------------
__global__ void k_init() {
    int i = blockIdx.x * blockDim.x + threadIdx.x;
    int stride = gridDim.x * blockDim.x;
    for (int t = i; t < NTOT * 128; t += stride) d_acc1[t] = 0.f;
    for (int t = i; t < NTOT * 2; t += stride) { d_amax1[t] = ENCNEG; d_den1[t] = 0.f; }
    for (int t = i; t < NTOT; t += stride)     { d_amax2[t] = ENCNEG; d_den2[t] = 0.f; }
    for (int t = i; t < BB * 64; t += stride)  d_acc2[t] = 0.f;
}

// ---------------- kernel: fused LN + collapsed linears -> xh1, s1, d1 ----------------
__global__ __launch_bounds__(256) void k_node1(const float* __restrict__ tf,
                                               const float* __restrict__ g_t, const float* __restrict__ b_t,
                                               const float* __restrict__ g_v, const float* __restrict__ b_v,
                                               const float* __restrict__ a1s, const float* __restrict__ a1d)
{
    __shared__ float sMt[39 * 128];
    __shared__ float sMv[25 * 128];
    __shared__ float sc[128];
    __shared__ float sas[128], sad[128];
    __shared__ float sgp[64], sbp[64];
    __shared__ float snorm[8][64];
    int tid = threadIdx.x;
    for (int t = tid; t < 39 * 128; t += 256) sMt[t] = d_Mt[t];
    for (int t = tid; t < 25 * 128; t += 256) sMv[t] = d_Mv[t];
    if (tid < 128) { sc[tid] = d_c[tid]; sas[tid] = a1s[tid]; sad[tid] = a1d[tid]; }
    if (tid < 64) {
        sgp[tid] = (tid < 39) ? g_t[tid] : g_v[tid - 39];
        sbp[tid] = (tid < 39) ? b_t[tid] : b_v[tid - 39];
    }
    __syncthreads();
    int w = tid >> 5, lane = tid & 31;
    int v = blockIdx.x * 8 + w;
    if (v >= NN) return;

    float2 p = ((const float2*)tf)[v * 32 + lane];
    int p0 = lane * 2, p1 = lane * 2 + 1;
    float st = 0, sst = 0, sv = 0, ssv = 0;
    if (p0 < 39) { st += p.x; sst += p.x * p.x; } else { sv += p.x; ssv += p.x * p.x; }
    if (p1 < 39) { st += p.y; sst += p.y * p.y; } else { sv += p.y; ssv += p.y * p.y; }
    #pragma unroll
    for (int o = 16; o; o >>= 1) {
        st  += __shfl_xor_sync(0xffffffffu, st, o);
        sst += __shfl_xor_sync(0xffffffffu, sst, o);
        sv  += __shfl_xor_sync(0xffffffffu, sv, o);
        ssv += __shfl_xor_sync(0xffffffffu, ssv, o);
    }
    float mt = st * (1.f / 39.f), vt = sst * (1.f / 39.f) - mt * mt;
    float mv = sv * (1.f / 25.f), vv = ssv * (1.f / 25.f) - mv * mv;
    float rt = rsqrtf(vt + 1e-5f), rv = rsqrtf(vv + 1e-5f);
    float n0 = (p0 < 39) ? (p.x - mt) * rt : (p.x - mv) * rv;
    float n1 = (p1 < 39) ? (p.y - mt) * rt : (p.y - mv) * rv;
    n0 = n0 * sgp[p0] + sbp[p0];
    n1 = n1 * sgp[p1] + sbp[p1];
    snorm[w][p0] = n0; snorm[w][p1] = n1;
    __syncwarp();

    int j0 = lane * 4;
    float4 acc = *(const float4*)&sc[j0];
    #pragma unroll
    for (int i = 0; i < 39; i++) {
        float x = snorm[w][i];
        float4 m = *(const float4*)&sMt[i * 128 + j0];
        acc.x += x * m.x; acc.y += x * m.y; acc.z += x * m.z; acc.w += x * m.w;
    }
    #pragma unroll
    for (int i = 0; i < 25; i++) {
        float x = snorm[w][39 + i];
        float4 m = *(const float4*)&sMv[i * 128 + j0];
        acc.x += x * m.x; acc.y += x * m.y; acc.z += x * m.z; acc.w += x * m.w;
    }
    *(float4*)&d_xh1[v * 128 + j0] = acc;

    float4 as4 = *(const float4*)&sas[j0];
    float4 ad4 = *(const float4*)&sad[j0];
    float ps = acc.x * as4.x + acc.y * as4.y + acc.z * as4.z + acc.w * as4.w;
    float pd = acc.x * ad4.x + acc.y * ad4.y + acc.z * ad4.z + acc.w * ad4.w;
    #pragma unroll
    for (int o = 8; o; o >>= 1) {
        ps += __shfl_xor_sync(0xffffffffu, ps, o);
        pd += __shfl_xor_sync(0xffffffffu, pd, o);
    }
    if (lane == 0)  { d_s1[v * 2]     = ps; d_d1[v * 2]     = pd; }
    if (lane == 16) { d_s1[v * 2 + 1] = ps; d_d1[v * 2 + 1] = pd; }
}

// ---------------- kernel: GAT1 max pass + emit src/dst ----------------
__global__ void k_edge1(const int* __restrict__ ei, float* __restrict__ out) {
    int e = blockIdx.x * blockDim.x + threadIdx.x;
    if (e >= ETOT) return;
    int s, d; edge_sd(e, ei, s, d);
    out[2048 + e] = (float)s;
    out[2048 + ETOT + e] = (float)d;
    float2 sv = *(const float2*)&d_s1[s * 2];
    float2 dv = *(const float2*)&d_d1[d * 2];
    atomicMax(&d_amax1[d * 2],     enc_f(lrelu(sv.x + dv.x)));
    atomicMax(&d_amax1[d * 2 + 1], enc_f(lrelu(sv.y + dv.y)));
}

// ---------------- kernel: GAT1 exp/den + vectorized numerator RED (warp per edge) ----------------
__global__ __launch_bounds__(256) void k_edge2(const int* __restrict__ ei) {
    int w = (blockIdx.x * 256 + threadIdx.x) >> 5;
    int lane = threadIdx.x & 31;
    if (w >= ETOT) return;
    int s, d; edge_sd(w, ei, s, d);
    float2 sv = *(const float2*)&d_s1[s * 2];
    float2 dv = *(const float2*)&d_d1[d * 2];
    int2 m = *(const int2*)&d_amax1[d * 2];
    float ex0 = expf(lrelu(sv.x + dv.x) - dec_f(m.x));
    float ex1 = expf(lrelu(sv.y + dv.y) - dec_f(m.y));
    if (lane == 0) {
        atomicAdd(&d_den1[d * 2],     ex0);
        atomicAdd(&d_den1[d * 2 + 1], ex1);
    }
    int j = lane * 4;
    float wg = (j < 64) ? ex0 : ex1;
    float4 x = *(const float4*)&d_xh1[s * 128 + j];
    float* p = &d_acc1[d * 128 + j];
    asm volatile("red.global.add.v4.f32 [%0], {%1,%2,%3,%4};"
                 :: "l"(p), "f"(wg * x.x), "f"(wg * x.y), "f"(wg * x.z), "f"(wg * x.w)
                 : "memory");
}

// ---------------- kernel: finish GAT1 (div+bias+relu) fused with GAT2 projection ----------------
__global__ __launch_bounds__(256) void k_node2(const float* __restrict__ W2, const float* __restrict__ b1,
                                               const float* __restrict__ a2s, const float* __restrict__ a2d)
{
    __shared__ float sW[128 * 64];
    __shared__ float sb1[128];
    __shared__ float sas[64], sad[64];
    __shared__ float sh[8][128];
    int tid = threadIdx.x;
    for (int t = tid; t < 128 * 64; t += 256) sW[t] = W2[t];
    if (tid < 128) sb1[tid] = b1[tid];
    if (tid < 64) { sas[tid] = a2s[tid]; sad[tid] = a2d[tid]; }
    __syncthreads();
    int w = tid >> 5, lane = tid & 31;
    int v = blockIdx.x * 8 + w;
    if (v >= NTOT) return;

    float2 den = *(const float2*)&d_den1[v * 2];
    float r0 = 1.f / (den.x + 1e-16f), r1 = 1.f / (den.y + 1e-16f);
    int j0 = lane * 4;
    float4 a = *(const float4*)&d_acc1[v * 128 + j0];
    float r = (j0 < 64) ? r0 : r1;
    a.x = fmaxf(a.x * r + sb1[j0 + 0], 0.f);
    a.y = fmaxf(a.y * r + sb1[j0 + 1], 0.f);
    a.z = fmaxf(a.z * r + sb1[j0 + 2], 0.f);
    a.w = fmaxf(a.w * r + sb1[j0 + 3], 0.f);
    sh[w][j0 + 0] = a.x; sh[w][j0 + 1] = a.y; sh[w][j0 + 2] = a.z; sh[w][j0 + 3] = a.w;
    __syncwarp();

    int c0 = lane * 2;
    float2 o = make_float2(0.f, 0.f);
    #pragma unroll 8
    for (int k = 0; k < 128; k++) {
        float x = sh[w][k];
        float2 mw = *(const float2*)&sW[k * 64 + c0];
        o.x += x * mw.x; o.y += x * mw.y;
    }
    *(float2*)&d_xh2[v * 64 + c0] = o;
    float ps = o.x * sas[c0] + o.y * sas[c0 + 1];
    float pd = o.x * sad[c0] + o.y * sad[c0 + 1];
    #pragma unroll
    for (int of = 16; of; of >>= 1) {
        ps += __shfl_xor_sync(0xffffffffu, ps, of);
        pd += __shfl_xor_sync(0xffffffffu, pd, of);
    }
    if (lane == 0) { d_s2[v] = ps; d_d2[v] = pd; }
}

// ---------------- kernel: GAT2 max pass ----------------
__global__ void k_edge3(const int* __restrict__ ei) {
    int e = blockIdx.x * blockDim.x + threadIdx.x;
    if (e >= ETOT) return;
    int s, d; edge_sd(e, ei, s, d);
    atomicMax(&d_amax2[d], enc_f(lrelu(d_s2[s] + d_d2[d])));
}

// ---------------- kernel: GAT2 exp/den, stash ex in att slot ----------------
__global__ void k_edge4(const int* __restrict__ ei, float* __restrict__ out) {
    int e = blockIdx.x * blockDim.x + threadIdx.x;
    if (e >= ETOT) return;
    int s, d; edge_sd(e, ei, s, d);
    float ex = expf(lrelu(d_s2[s] + d_d2[d]) - dec_f(d_amax2[d]));
    atomicAdd(&d_den2[d], ex);
    out[2048 + 2 * ETOT + e] = ex;
}

// ---------------- kernel: aggregate GAT2 messages into glb nodes only ----------------
__global__ __launch_bounds__(256) void k_glbagg(const float* __restrict__ out) {
    int w = (blockIdx.x * 256 + threadIdx.x) >> 5;
    int lane = threadIdx.x & 31;
    if (w >= NN + BB) return;
    int s, g, e;
    if (w < NN) { s = w; g = w / NPER; e = EE + NN + w; }
    else        { g = w - NN; s = NN + g; e = EE + 3 * NN + g; }
    float ex = out[2048 + 2 * ETOT + e];
    int c0 = lane * 2;
    float2 x = *(const float2*)&d_xh2[s * 64 + c0];
    float* p = &d_acc2[g * 64 + c0];
    asm volatile("red.global.add.v2.f32 [%0], {%1,%2};"
                 :: "l"(p), "f"(ex * x.x), "f"(ex * x.y) : "memory");
}

// ---------------- kernel: finalize att (divide by den) ----------------
__global__ void k_edge5(const int* __restrict__ ei, float* __restrict__ out) {
    int e = blockIdx.x * blockDim.x + threadIdx.x;
    if (e >= ETOT) return;
    int s, d; edge_sd(e, ei, s, d);
    int idx = 2048 + 2 * ETOT + e;
    out[idx] = out[idx] / (d_den2[d] + 1e-16f);
}

// ---------------- kernel: finalize tree_glb ----------------
__global__ void k_fin(const float* __restrict__ b2, float* __restrict__ out) {
    int t = blockIdx.x * blockDim.x + threadIdx.x;
    if (t >= BB * 64) return;
    int g = t >> 6, j = t & 63;
    out[t] = d_acc2[t] / (d_den2[NN + g] + 1e-16f) + b2[j];
}

// ---------------- launch ----------------
extern "C" void kernel_launch(void* const* d_in, const int* in_sizes, int n_in,
                              void* d_out, int out_size) {
    const float* tree_feature = (const float*)d_in[0];
    const int*   edge_index   = (const int*)d_in[1];
    const float* ln_tree_g  = (const float*)d_in[4];
    const float* ln_tree_b  = (const float*)d_in[5];
    const float* lin_tree_W = (const float*)d_in[6];
    const float* lin_tree_b = (const float*)d_in[7];
    const float* ln_var_g   = (const float*)d_in[8];
    const float* ln_var_b   = (const float*)d_in[9];
    const float* lin_var_W  = (const float*)d_in[10];
    const float* lin_var_b  = (const float*)d_in[11];
    const float* glb_W      = (const float*)d_in[12];
    const float* glb_b      = (const float*)d_in[13];
    const float* glbNode    = (const float*)d_in[14];
    const float* gat1_W     = (const float*)d_in[15];
    const float* gat1_as    = (const float*)d_in[16];
    const float* gat1_ad    = (const float*)d_in[17];
    const float* gat1_b     = (const float*)d_in[18];
    const float* gat2_W     = (const float*)d_in[19];
    const float* gat2_as    = (const float*)d_in[20];
    const float* gat2_ad    = (const float*)d_in[21];
    const float* gat2_b     = (const float*)d_in[22];
    float* out = (float*)d_out;

    k_pre<<<1, 128>>>(lin_tree_W, lin_tree_b, lin_var_W, lin_var_b,
                      glb_W, glb_b, glbNode, gat1_W, gat1_as, gat1_ad);
    k_init<<<1184, 256>>>();
    k_node1<<<(NN + 7) / 8, 256>>>(tree_feature, ln_tree_g, ln_tree_b,
                                   ln_var_g, ln_var_b, gat1_as, gat1_ad);
    k_edge1<<<(ETOT + 255) / 256, 256>>>(edge_index, out);
    k_edge2<<<(ETOT * 32 + 255) / 256, 256>>>(edge_index);
    k_node2<<<(NTOT + 7) / 8, 256>>>(gat2_W, gat1_b, gat2_as, gat2_ad);
    k_edge3<<<(ETOT + 255) / 256, 256>>>(edge_index);
    k_edge4<<<(ETOT + 255) / 256, 256>>>(edge_index, out);
    k_glbagg<<<((NN + BB) * 32 + 255) / 256, 256>>>(out);
    k_edge5<<<(ETOT + 255) / 256, 256>>>(edge_index, out);
    k_fin<<<8, 256>>>(gat2_b, out);
}

// round 2
// speedup vs baseline: 2.4989x; 2.4989x over previous
#include <cuda_runtime.h>
#include <cuda_bf16.h>
#include <math.h>

#define NN   100000
#define BB   32
#define NPER 3125
#define EE   200000
#define NTOT 100032
#define ETOT 500032
#define CHUNK 125
#define NCHUNK 25

// ---------------- scratch ----------------
__device__ float d_Mv[25 * 128];
__device__ float d_Mt[39 * 128];
__device__ float d_c[128];
__device__ float d_G[128 * 128];
__device__ float d_xh1[NTOT * 128];
__device__ float d_s1[NTOT * 2];
__device__ float d_d1[NTOT * 2];
__device__ int   d_amax1[NTOT * 2];
__device__ float d_den1[NTOT * 2];
__device__ float d_acc1[NTOT * 128];
__device__ float d_xh2[NTOT * 64];
__device__ float d_s2[NTOT];
__device__ float d_d2[NTOT];
__device__ int   d_amax2[NTOT];
__device__ float d_den2[NTOT];
__device__ float d_acc2[BB * 64];

// ---------------- helpers ----------------
__device__ __forceinline__ int enc_f(float f) {
    int i = __float_as_int(f);
    return i >= 0 ? i : (i ^ 0x7FFFFFFF);
}
__device__ __forceinline__ float dec_f(int i) {
    return __int_as_float(i >= 0 ? i : (i ^ 0x7FFFFFFF));
}
__device__ __forceinline__ float lrelu(float x) { return x > 0.f ? x : 0.2f * x; }

__device__ __forceinline__ void edge_sd(int e, const int* __restrict__ ei, int& s, int& d) {
    if (e < EE)               { s = ei[e]; d = ei[EE + e]; }
    else if (e < EE + NN)     { int i = e - EE;          d = i; s = NN + i / NPER; }
    else if (e < EE + 2 * NN) { int i = e - EE - NN;     s = i; d = NN + i / NPER; }
    else                      { int i = e - EE - 2 * NN; s = i; d = i; }
}

// ---------------- precompute collapsed weights + glb features ----------------
__global__ void k_pre(const float* __restrict__ lin_tree_W, const float* __restrict__ lin_tree_b,
                      const float* __restrict__ lin_var_W,  const float* __restrict__ lin_var_b,
                      const float* __restrict__ glb_W,      const float* __restrict__ glb_b,
                      const float* __restrict__ glbNode,    const float* __restrict__ gat1_W,
                      const float* __restrict__ a1s,        const float* __restrict__ a1d)
{
    __shared__ float sbias[64];
    __shared__ float sxg[128];
    __shared__ float sres[4];
    int j = threadIdx.x; // 0..127
    if (j < 64) {
        float acc = glb_b[j];
        for (int k = 0; k < 64; k++)
            acc += lin_var_b[k] * glb_W[k * 64 + j] + lin_tree_b[k] * glb_W[(64 + k) * 64 + j];
        sbias[j] = acc;
    }
    __syncthreads();
    {
        float cj = 0.f;
        for (int m = 0; m < 64; m++) cj += sbias[m] * gat1_W[m * 128 + j];
        d_c[j] = cj;
    }
    for (int k = 0; k < 128; k++) {
        float a = 0.f;
        for (int m = 0; m < 64; m++) a += glb_W[k * 64 + m] * gat1_W[m * 128 + j];
        d_G[k * 128 + j] = a;
    }
    for (int i = 0; i < 25; i++) {
        float a = 0.f;
        for (int k = 0; k < 64; k++) a += lin_var_W[i * 64 + k] * d_G[k * 128 + j];
        d_Mv[i * 128 + j] = a;
    }
    for (int i = 0; i < 39; i++) {
        float a = 0.f;
        for (int k = 0; k < 64; k++) a += lin_tree_W[i * 64 + k] * d_G[(64 + k) * 128 + j];
        d_Mt[i * 128 + j] = a;
    }
    float xg = 0.f;
    for (int m = 0; m < 64; m++) xg += glbNode[m] * gat1_W[m * 128 + j];
    for (int g = 0; g < BB; g++) d_xh1[(NN + g) * 128 + j] = xg;
    sxg[j] = xg;
    __syncthreads();
    if (j == 0) {
        float s0 = 0, s1 = 0, dd0 = 0, dd1 = 0;
        for (int c = 0; c < 64; c++) {
            s0 += sxg[c] * a1s[c];           dd0 += sxg[c] * a1d[c];
            s1 += sxg[64 + c] * a1s[64 + c]; dd1 += sxg[64 + c] * a1d[64 + c];
        }
        sres[0] = s0; sres[1] = s1; sres[2] = dd0; sres[3] = dd1;
    }
    __syncthreads();
    if (j < BB) {
        d_s1[(NN + j) * 2]     = sres[0];
        d_s1[(NN + j) * 2 + 1] = sres[1];
        d_d1[(NN + j) * 2]     = sres[2];
        d_d1[(NN + j) * 2 + 1] = sres[3];
    }
}

// ---------------- zero accumulators ----------------
__global__ void k_zero() {
    int i = blockIdx.x * blockDim.x + threadIdx.x;
    int stride = gridDim.x * blockDim.x;
    float4 z4 = make_float4(0.f, 0.f, 0.f, 0.f);
    for (int t = i; t < NTOT * 32; t += stride) ((float4*)d_acc1)[t] = z4;
    for (int t = i; t < NTOT * 2; t += stride) d_den1[t] = 0.f;
    for (int t = i; t < NTOT; t += stride)     d_den2[t] = 0.f;
    for (int t = i; t < BB * 64; t += stride)  d_acc2[t] = 0.f;
}

// ---------------- fused LN + collapsed linears -> xh1, s1, d1, amax1 init ----------------
__global__ __launch_bounds__(256) void k_node1(const float* __restrict__ tf,
                                               const float* __restrict__ g_t, const float* __restrict__ b_t,
                                               const float* __restrict__ g_v, const float* __restrict__ b_v,
                                               const float* __restrict__ a1s, const float* __restrict__ a1d)
{
    __shared__ float sMt[39 * 128];
    __shared__ float sMv[25 * 128];
    __shared__ float sc[128];
    __shared__ float sas[128], sad[128];
    __shared__ float sgp[64], sbp[64];
    __shared__ float snorm[8][64];
    int tid = threadIdx.x;
    for (int t = tid; t < 39 * 128; t += 256) sMt[t] = d_Mt[t];
    for (int t = tid; t < 25 * 128; t += 256) sMv[t] = d_Mv[t];
    if (tid < 128) { sc[tid] = d_c[tid]; sas[tid] = a1s[tid]; sad[tid] = a1d[tid]; }
    if (tid < 64) {
        sgp[tid] = (tid < 39) ? g_t[tid] : g_v[tid - 39];
        sbp[tid] = (tid < 39) ? b_t[tid] : b_v[tid - 39];
    }
    __syncthreads();
    int w = tid >> 5, lane = tid & 31;
    int v = blockIdx.x * 8 + w;
    if (v >= NN) return;

    float2 p = ((const float2*)tf)[v * 32 + lane];
    int p0 = lane * 2, p1 = lane * 2 + 1;
    float st = 0, sst = 0, sv = 0, ssv = 0;
    if (p0 < 39) { st += p.x; sst += p.x * p.x; } else { sv += p.x; ssv += p.x * p.x; }
    if (p1 < 39) { st += p.y; sst += p.y * p.y; } else { sv += p.y; ssv += p.y * p.y; }
    #pragma unroll
    for (int o = 16; o; o >>= 1) {
        st  += __shfl_xor_sync(0xffffffffu, st, o);
        sst += __shfl_xor_sync(0xffffffffu, sst, o);
        sv  += __shfl_xor_sync(0xffffffffu, sv, o);
        ssv += __shfl_xor_sync(0xffffffffu, ssv, o);
    }
    float mt = st * (1.f / 39.f), vt = sst * (1.f / 39.f) - mt * mt;
    float mv = sv * (1.f / 25.f), vv = ssv * (1.f / 25.f) - mv * mv;
    float rt = rsqrtf(vt + 1e-5f), rv = rsqrtf(vv + 1e-5f);
    float n0 = (p0 < 39) ? (p.x - mt) * rt : (p.x - mv) * rv;
    float n1 = (p1 < 39) ? (p.y - mt) * rt : (p.y - mv) * rv;
    n0 = n0 * sgp[p0] + sbp[p0];
    n1 = n1 * sgp[p1] + sbp[p1];
    snorm[w][p0] = n0; snorm[w][p1] = n1;
    __syncwarp();

    int j0 = lane * 4;
    float4 acc = *(const float4*)&sc[j0];
    #pragma unroll
    for (int i = 0; i < 39; i++) {
        float x = snorm[w][i];
        float4 m = *(const float4*)&sMt[i * 128 + j0];
        acc.x += x * m.x; acc.y += x * m.y; acc.z += x * m.z; acc.w += x * m.w;
    }
    #pragma unroll
    for (int i = 0; i < 25; i++) {
        float x = snorm[w][39 + i];
        float4 m = *(const float4*)&sMv[i * 128 + j0];
        acc.x += x * m.x; acc.y += x * m.y; acc.z += x * m.z; acc.w += x * m.w;
    }
    *(float4*)&d_xh1[v * 128 + j0] = acc;

    float4 as4 = *(const float4*)&sas[j0];
    float4 ad4 = *(const float4*)&sad[j0];
    float ps = acc.x * as4.x + acc.y * as4.y + acc.z * as4.z + acc.w * as4.w;
    float pd = acc.x * ad4.x + acc.y * ad4.y + acc.z * ad4.z + acc.w * ad4.w;
    #pragma unroll
    for (int o = 8; o; o >>= 1) {
        ps += __shfl_xor_sync(0xffffffffu, ps, o);
        pd += __shfl_xor_sync(0xffffffffu, pd, o);
    }
    // init amax with deterministic incoming edges (glb->v and self-loop)
    if (lane == 0) {
        d_s1[v * 2] = ps; d_d1[v * 2] = pd;
        float s1g = d_s1[NN * 2];
        d_amax1[v * 2] = enc_f(fmaxf(lrelu(s1g + pd), lrelu(ps + pd)));
    }
    if (lane == 16) {
        d_s1[v * 2 + 1] = ps; d_d1[v * 2 + 1] = pd;
        float s1g = d_s1[NN * 2 + 1];
        d_amax1[v * 2 + 1] = enc_f(fmaxf(lrelu(s1g + pd), lrelu(ps + pd)));
    }
}

// ---------------- GAT1 max pass: random edges only ----------------
__global__ void k_e1max(const int* __restrict__ ei) {
    int e = blockIdx.x * blockDim.x + threadIdx.x;
    if (e >= EE) return;
    int s = ei[e], d = ei[EE + e];
    float2 sv = *(const float2*)&d_s1[s * 2];
    float2 dv = *(const float2*)&d_d1[d * 2];
    atomicMax(&d_amax1[d * 2],     enc_f(lrelu(sv.x + dv.x)));
    atomicMax(&d_amax1[d * 2 + 1], enc_f(lrelu(sv.y + dv.y)));
}

// ---------------- GAT1 glb amax: segmented max per graph ----------------
__global__ __launch_bounds__(256) void k_glbmax1() {
    __shared__ float sm0[256], sm1[256];
    int g = blockIdx.x, tid = threadIdx.x;
    float d1g0 = d_d1[NN * 2], d1g1 = d_d1[NN * 2 + 1];
    float m0 = -1e30f, m1 = -1e30f;
    for (int i = g * NPER + tid; i < (g + 1) * NPER; i += 256) {
        m0 = fmaxf(m0, lrelu(d_s1[i * 2]     + d1g0));
        m1 = fmaxf(m1, lrelu(d_s1[i * 2 + 1] + d1g1));
    }
    sm0[tid] = m0; sm1[tid] = m1;
    __syncthreads();
    for (int o = 128; o; o >>= 1) {
        if (tid < o) {
            sm0[tid] = fmaxf(sm0[tid], sm0[tid + o]);
            sm1[tid] = fmaxf(sm1[tid], sm1[tid + o]);
        }
        __syncthreads();
    }
    if (tid == 0) {
        float s1g0 = d_s1[NN * 2], s1g1 = d_s1[NN * 2 + 1];
        d_amax1[(NN + g) * 2]     = enc_f(fmaxf(sm0[0], lrelu(s1g0 + d1g0)));
        d_amax1[(NN + g) * 2 + 1] = enc_f(fmaxf(sm1[0], lrelu(s1g1 + d1g1)));
    }
}

// ---------------- GAT1 accumulate: random edges, warp per edge ----------------
__global__ __launch_bounds__(256) void k_e2acc(const int* __restrict__ ei) {
    int w = (blockIdx.x * 256 + threadIdx.x) >> 5;
    int lane = threadIdx.x & 31;
    if (w >= EE) return;
    int s = ei[w], d = ei[EE + w];
    float2 sv = *(const float2*)&d_s1[s * 2];
    float2 dv = *(const float2*)&d_d1[d * 2];
    int2 m = *(const int2*)&d_amax1[d * 2];
    float ex0 = expf(lrelu(sv.x + dv.x) - dec_f(m.x));
    float ex1 = expf(lrelu(sv.y + dv.y) - dec_f(m.y));
    if (lane == 0) {
        atomicAdd(&d_den1[d * 2],     ex0);
        atomicAdd(&d_den1[d * 2 + 1], ex1);
    }
    int j = lane * 4;
    float wg = (j < 64) ? ex0 : ex1;
    float4 x = *(const float4*)&d_xh1[s * 128 + j];
    float* p = &d_acc1[d * 128 + j];
    asm volatile("red.global.add.v4.f32 [%0], {%1,%2,%3,%4};"
                 :: "l"(p), "f"(wg * x.x), "f"(wg * x.y), "f"(wg * x.z), "f"(wg * x.w)
                 : "memory");
}

// ---------------- GAT1 glb den+numerator: chunked segmented reduction ----------------
__global__ __launch_bounds__(128) void k_glbacc1() {
    int g = blockIdx.x / NCHUNK, c = blockIdx.x % NCHUNK;
    int j = threadIdx.x;
    int h = j >> 6;
    float d1g = d_d1[NN * 2 + h];
    float amax = dec_f(d_amax1[(NN + g) * 2 + h]);
    int i0 = g * NPER + c * CHUNK;
    float acc = 0.f, den = 0.f;
    for (int i = i0; i < i0 + CHUNK; i++) {
        float ex = expf(lrelu(d_s1[i * 2 + h] + d1g) - amax);
        acc += ex * d_xh1[i * 128 + j];
        den += ex;
    }
    if (c == 0) { // self-loop
        float exs = expf(lrelu(d_s1[NN * 2 + h] + d1g) - amax);
        acc += exs * d_xh1[NN * 128 + j];
        den += exs;
    }
    atomicAdd(&d_acc1[(NN + g) * 128 + j], acc);
    if (j == 0 || j == 64) atomicAdd(&d_den1[(NN + g) * 2 + h], den);
}

// ---------------- finish GAT1 + GAT2 projection ----------------
__global__ __launch_bounds__(256) void k_node2(const float* __restrict__ W2, const float* __restrict__ b1,
                                               const float* __restrict__ a2s, const float* __restrict__ a2d)
{
    __shared__ float sW[128 * 64];
    __shared__ float sb1[128];
    __shared__ float sas[64], sad[64];
    __shared__ float sh[8][128];
    int tid = threadIdx.x;
    for (int t = tid; t < 128 * 64; t += 256) sW[t] = W2[t];
    if (tid < 128) sb1[tid] = b1[tid];
    if (tid < 64) { sas[tid] = a2s[tid]; sad[tid] = a2d[tid]; }
    __syncthreads();
    int w = tid >> 5, lane = tid & 31;
    int v = blockIdx.x * 8 + w;
    if (v >= NTOT) return;

    int j0 = lane * 4;
    int h = (j0 >= 64);
    float den_h, exg = 0.f, exs = 0.f;
    float2 den2r = *(const float2*)&d_den1[v * 2];
    float den_rand = h ? den2r.y : den2r.x;
    float4 num = *(const float4*)&d_acc1[v * 128 + j0];
    if (v < NN) {
        float amax = dec_f(d_amax1[v * 2 + h]);
        float s1g  = d_s1[NN * 2 + h];
        float s1v  = d_s1[v * 2 + h];
        float d1v  = d_d1[v * 2 + h];
        exg = expf(lrelu(s1g + d1v) - amax);
        exs = expf(lrelu(s1v + d1v) - amax);
        float4 xg = *(const float4*)&d_xh1[NN * 128 + j0];
        float4 xv = *(const float4*)&d_xh1[v * 128 + j0];
        num.x += exg * xg.x + exs * xv.x;
        num.y += exg * xg.y + exs * xv.y;
        num.z += exg * xg.z + exs * xv.z;
        num.w += exg * xg.w + exs * xv.w;
        den_h = den_rand + exg + exs;
    } else {
        den_h = den_rand;
    }
    float r = 1.f / (den_h + 1e-16f);
    float4 a;
    a.x = fmaxf(num.x * r + sb1[j0 + 0], 0.f);
    a.y = fmaxf(num.y * r + sb1[j0 + 1], 0.f);
    a.z = fmaxf(num.z * r + sb1[j0 + 2], 0.f);
    a.w = fmaxf(num.w * r + sb1[j0 + 3], 0.f);
    sh[w][j0 + 0] = a.x; sh[w][j0 + 1] = a.y; sh[w][j0 + 2] = a.z; sh[w][j0 + 3] = a.w;
    __syncwarp();

    int c0 = lane * 2;
    float2 o = make_float2(0.f, 0.f);
    #pragma unroll 8
    for (int k = 0; k < 128; k++) {
        float x = sh[w][k];
        float2 mw = *(const float2*)&sW[k * 64 + c0];
        o.x += x * mw.x; o.y += x * mw.y;
    }
    *(float2*)&d_xh2[v * 64 + c0] = o;
    float ps = o.x * sas[c0] + o.y * sas[c0 + 1];
    float pd = o.x * sad[c0] + o.y * sad[c0 + 1];
    #pragma unroll
    for (int of = 16; of; of >>= 1) {
        ps += __shfl_xor_sync(0xffffffffu, ps, of);
        pd += __shfl_xor_sync(0xffffffffu, pd, of);
    }
    if (lane == 0) { d_s2[v] = ps; d_d2[v] = pd; }
}

// ---------------- GAT2 amax init (deterministic edges) for tree nodes ----------------
__global__ void k_amax2init() {
    int i = blockIdx.x * blockDim.x + threadIdx.x;
    if (i >= NN) return;
    int g = i / NPER;
    float s2g = d_s2[NN + g];
    float s2i = d_s2[i];
    float d2i = d_d2[i];
    d_amax2[i] = enc_f(fmaxf(lrelu(s2g + d2i), lrelu(s2i + d2i)));
}

// ---------------- GAT2 max pass: random edges ----------------
__global__ void k_e3max(const int* __restrict__ ei) {
    int e = blockIdx.x * blockDim.x + threadIdx.x;
    if (e >= EE) return;
    int s = ei[e], d = ei[EE + e];
    atomicMax(&d_amax2[d], enc_f(lrelu(d_s2[s] + d_d2[d])));
}

// ---------------- GAT2 glb amax ----------------
__global__ __launch_bounds__(256) void k_glbmax2() {
    __shared__ float sm[256];
    int g = blockIdx.x, tid = threadIdx.x;
    float d2g = d_d2[NN + g];
    float m = -1e30f;
    for (int i = g * NPER + tid; i < (g + 1) * NPER; i += 256)
        m = fmaxf(m, lrelu(d_s2[i] + d2g));
    sm[tid] = m;
    __syncthreads();
    for (int o = 128; o; o >>= 1) {
        if (tid < o) sm[tid] = fmaxf(sm[tid], sm[tid + o]);
        __syncthreads();
    }
    if (tid == 0)
        d_amax2[NN + g] = enc_f(fmaxf(sm[0], lrelu(d_s2[NN + g] + d2g)));
}

// ---------------- GAT2 den deterministic part for tree nodes (store) ----------------
__global__ void k_dentree2() {
    int i = blockIdx.x * blockDim.x + threadIdx.x;
    if (i >= NN) return;
    int g = i / NPER;
    float amax = dec_f(d_amax2[i]);
    float d2i = d_d2[i];
    d_den2[i] = expf(lrelu(d_s2[NN + g] + d2i) - amax) + expf(lrelu(d_s2[i] + d2i) - amax);
}

// ---------------- GAT2 den random edges ----------------
__global__ void k_e4den(const int* __restrict__ ei) {
    int e = blockIdx.x * blockDim.x + threadIdx.x;
    if (e >= EE) return;
    int s = ei[e], d = ei[EE + e];
    atomicAdd(&d_den2[d], expf(lrelu(d_s2[s] + d_d2[d]) - dec_f(d_amax2[d])));
}

// ---------------- GAT2 glb den + numerator: chunked segmented reduction ----------------
__global__ __launch_bounds__(64) void k_glbacc2() {
    int g = blockIdx.x / NCHUNK, c = blockIdx.x % NCHUNK;
    int j = threadIdx.x;
    float d2g = d_d2[NN + g];
    float amax = dec_f(d_amax2[NN + g]);
    int i0 = g * NPER + c * CHUNK;
    float acc = 0.f, den = 0.f;
    for (int i = i0; i < i0 + CHUNK; i++) {
        float ex = expf(lrelu(d_s2[i] + d2g) - amax);
        acc += ex * d_xh2[i * 64 + j];
        den += ex;
    }
    if (c == 0) { // self-loop
        float exs = expf(lrelu(d_s2[NN + g] + d2g) - amax);
        acc += exs * d_xh2[(NN + g) * 64 + j];
        den += exs;
    }
    atomicAdd(&d_acc2[g * 64 + j], acc);
    if (j == 0) atomicAdd(&d_den2[NN + g], den);
}

// ---------------- emit src/dst ----------------
__global__ void k_emit(const int* __restrict__ ei, float* __restrict__ out) {
    int e = blockIdx.x * blockDim.x + threadIdx.x;
    if (e >= ETOT) return;
    int s, d; edge_sd(e, ei, s, d);
    out[2048 + e] = (float)s;
    out[2048 + ETOT + e] = (float)d;
}

// ---------------- final attention weights ----------------
__global__ void k_att(const int* __restrict__ ei, float* __restrict__ out) {
    int e = blockIdx.x * blockDim.x + threadIdx.x;
    if (e >= ETOT) return;
    int s, d; edge_sd(e, ei, s, d);
    float ex = expf(lrelu(d_s2[s] + d_d2[d]) - dec_f(d_amax2[d]));
    out[2048 + 2 * ETOT + e] = ex / (d_den2[d] + 1e-16f);
}

// ---------------- finalize tree_glb ----------------
__global__ void k_fin(const float* __restrict__ b2, float* __restrict__ out) {
    int t = blockIdx.x * blockDim.x + threadIdx.x;
    if (t >= BB * 64) return;
    int g = t >> 6, j = t & 63;
    out[t] = d_acc2[t] / (d_den2[NN + g] + 1e-16f) + b2[j];
}

// ---------------- launch ----------------
extern "C" void kernel_launch(void* const* d_in, const int* in_sizes, int n_in,
                              void* d_out, int out_size) {
    const float* tree_feature = (const float*)d_in[0];
    const int*   edge_index   = (const int*)d_in[1];
    const float* ln_tree_g  = (const float*)d_in[4];
    const float* ln_tree_b  = (const float*)d_in[5];
    const float* lin_tree_W = (const float*)d_in[6];
    const float* lin_tree_b = (const float*)d_in[7];
    const float* ln_var_g   = (const float*)d_in[8];
    const float* ln_var_b   = (const float*)d_in[9];
    const float* lin_var_W  = (const float*)d_in[10];
    const float* lin_var_b  = (const float*)d_in[11];
    const float* glb_W      = (const float*)d_in[12];
    const float* glb_b      = (const float*)d_in[13];
    const float* glbNode    = (const float*)d_in[14];
    const float* gat1_W     = (const float*)d_in[15];
    const float* gat1_as    = (const float*)d_in[16];
    const float* gat1_ad    = (const float*)d_in[17];
    const float* gat1_b     = (const float*)d_in[18];
    const float* gat2_W     = (const float*)d_in[19];
    const float* gat2_as    = (const float*)d_in[20];
    const float* gat2_ad    = (const float*)d_in[21];
    const float* gat2_b     = (const float*)d_in[22];
    float* out = (float*)d_out;

    k_pre<<<1, 128>>>(lin_tree_W, lin_tree_b, lin_var_W, lin_var_b,
                      glb_W, glb_b, glbNode, gat1_W, gat1_as, gat1_ad);
    k_zero<<<1184, 256>>>();
    k_node1<<<(NN + 7) / 8, 256>>>(tree_feature, ln_tree_g, ln_tree_b,
                                   ln_var_g, ln_var_b, gat1_as, gat1_ad);
    k_e1max<<<(EE + 255) / 256, 256>>>(edge_index);
    k_glbmax1<<<BB, 256>>>();
    k_e2acc<<<(EE * 32 + 255) / 256, 256>>>(edge_index);
    k_glbacc1<<<BB * NCHUNK, 128>>>();
    k_node2<<<(NTOT + 7) / 8, 256>>>(gat2_W, gat1_b, gat2_as, gat2_ad);
    k_amax2init<<<(NN + 255) / 256, 256>>>();
    k_e3max<<<(EE + 255) / 256, 256>>>(edge_index);
    k_glbmax2<<<BB, 256>>>();
    k_dentree2<<<(NN + 255) / 256, 256>>>();
    k_e4den<<<(EE + 255) / 256, 256>>>(edge_index);
    k_glbacc2<<<BB * NCHUNK, 64>>>();
    k_emit<<<(ETOT + 255) / 256, 256>>>(edge_index, out);
    k_att<<<(ETOT + 255) / 256, 256>>>(edge_index, out);
    k_fin<<<8, 256>>>(gat2_b, out);
}

// round 3
// speedup vs baseline: 3.8786x; 1.5521x over previous
#include <cuda_runtime.h>
#include <cuda_bf16.h>
#include <math.h>

#define NN   100000
#define BB   32
#define NPER 3125
#define EE   200000
#define NTOT 100032
#define ETOT 500032
#define CHUNK 25
#define NCHUNK 125

// ---------------- scratch ----------------
__device__ float d_M[64 * 128];      // combined collapsed matrix (rows 0..38 tree, 39..63 var)
__device__ float d_c[128];
__device__ float d_G[128 * 128];
__device__ float d_xh1[NTOT * 128];
__device__ float d_s1[NTOT * 2];
__device__ float d_d1[NTOT * 2];
__device__ float d_den1[NTOT * 2];
__device__ float d_acc1[NTOT * 128];
__device__ float d_xh2[NTOT * 64];
__device__ float d_s2[NTOT];
__device__ float d_d2[NTOT];
__device__ float d_den2[NTOT];
__device__ float d_acc2[BB * 64];

// ---------------- helpers ----------------
__device__ __forceinline__ float lrelu(float x) { return x > 0.f ? x : 0.2f * x; }

__device__ __forceinline__ void edge_sd(int e, const int* __restrict__ ei, int& s, int& d) {
    if (e < EE)               { s = ei[e]; d = ei[EE + e]; }
    else if (e < EE + NN)     { int i = e - EE;          d = i; s = NN + i / NPER; }
    else if (e < EE + 2 * NN) { int i = e - EE - NN;     s = i; d = NN + i / NPER; }
    else                      { int i = e - EE - 2 * NN; s = i; d = i; }
}

// packed f32x2 helpers
__device__ __forceinline__ unsigned long long f2pk(float lo, float hi) {
    unsigned long long r;
    asm("mov.b64 %0, {%1, %2};" : "=l"(r) : "f"(lo), "f"(hi));
    return r;
}
__device__ __forceinline__ void f2fma(unsigned long long& d, unsigned long long a, unsigned long long b) {
    asm("fma.rn.f32x2 %0, %1, %2, %0;" : "+l"(d) : "l"(a), "l"(b));
}
__device__ __forceinline__ float2 f2up(unsigned long long v) {
    float2 r;
    asm("mov.b64 {%0, %1}, %2;" : "=f"(r.x), "=f"(r.y) : "l"(v));
    return r;
}

// ---------------- precompute collapsed weights + glb features + zero glb accum ----------------
__global__ void k_pre(const float* __restrict__ lin_tree_W, const float* __restrict__ lin_tree_b,
                      const float* __restrict__ lin_var_W,  const float* __restrict__ lin_var_b,
                      const float* __restrict__ glb_W,      const float* __restrict__ glb_b,
                      const float* __restrict__ glbNode,    const float* __restrict__ gat1_W,
                      const float* __restrict__ a1s,        const float* __restrict__ a1d)
{
    __shared__ float sbias[64];
    __shared__ float sxg[128];
    __shared__ float sres[4];
    int j = threadIdx.x; // 0..127
    if (j < 64) {
        float acc = glb_b[j];
        for (int k = 0; k < 64; k++)
            acc += lin_var_b[k] * glb_W[k * 64 + j] + lin_tree_b[k] * glb_W[(64 + k) * 64 + j];
        sbias[j] = acc;
    }
    __syncthreads();
    {
        float cj = 0.f;
        for (int m = 0; m < 64; m++) cj += sbias[m] * gat1_W[m * 128 + j];
        d_c[j] = cj;
    }
    for (int k = 0; k < 128; k++) {
        float a = 0.f;
        for (int m = 0; m < 64; m++) a += glb_W[k * 64 + m] * gat1_W[m * 128 + j];
        d_G[k * 128 + j] = a;
    }
    // combined M: rows 0..38 = lin_tree_W @ G[64:128], rows 39..63 = lin_var_W @ G[0:64]
    for (int i = 0; i < 39; i++) {
        float a = 0.f;
        for (int k = 0; k < 64; k++) a += lin_tree_W[i * 64 + k] * d_G[(64 + k) * 128 + j];
        d_M[i * 128 + j] = a;
    }
    for (int i = 0; i < 25; i++) {
        float a = 0.f;
        for (int k = 0; k < 64; k++) a += lin_var_W[i * 64 + k] * d_G[k * 128 + j];
        d_M[(39 + i) * 128 + j] = a;
    }
    float xg = 0.f;
    for (int m = 0; m < 64; m++) xg += glbNode[m] * gat1_W[m * 128 + j];
    for (int g = 0; g < BB; g++) {
        d_xh1[(NN + g) * 128 + j] = xg;
        d_acc1[(NN + g) * 128 + j] = 0.f;
    }
    sxg[j] = xg;
    if (j < 64) d_den1[NN * 2 + j] = 0.f;
    if (j < BB) d_den2[NN + j] = 0.f;
    for (int t = j; t < BB * 64; t += 128) d_acc2[t] = 0.f;
    __syncthreads();
    if (j == 0) {
        float s0 = 0, s1 = 0, dd0 = 0, dd1 = 0;
        for (int c = 0; c < 64; c++) {
            s0 += sxg[c] * a1s[c];           dd0 += sxg[c] * a1d[c];
            s1 += sxg[64 + c] * a1s[64 + c]; dd1 += sxg[64 + c] * a1d[64 + c];
        }
        sres[0] = s0; sres[1] = s1; sres[2] = dd0; sres[3] = dd1;
    }
    __syncthreads();
    if (j < BB) {
        d_s1[(NN + j) * 2]     = sres[0];
        d_s1[(NN + j) * 2 + 1] = sres[1];
        d_d1[(NN + j) * 2]     = sres[2];
        d_d1[(NN + j) * 2 + 1] = sres[3];
    }
}

// ---------------- fused LN + collapsed GEMM + det-edge init (32 nodes/block) ----------------
__global__ __launch_bounds__(256) void k_node1(const float* __restrict__ tf,
                                               const float* __restrict__ g_t, const float* __restrict__ b_t,
                                               const float* __restrict__ g_v, const float* __restrict__ b_v,
                                               const float* __restrict__ a1s, const float* __restrict__ a1d)
{
    __shared__ float sM[64 * 128];
    __shared__ float sc[128], sas[128], sad[128], sxg[128];
    __shared__ float sgp[64], sbp[64];
    __shared__ float sglb[2];
    __shared__ float snorm[32][64];
    int tid = threadIdx.x;
    for (int t = tid; t < 64 * 128; t += 256) sM[t] = d_M[t];
    if (tid < 128) {
        sc[tid] = d_c[tid]; sas[tid] = a1s[tid]; sad[tid] = a1d[tid];
        sxg[tid] = d_xh1[NN * 128 + tid];
    }
    if (tid < 64) {
        sgp[tid] = (tid < 39) ? g_t[tid] : g_v[tid - 39];
        sbp[tid] = (tid < 39) ? b_t[tid] : b_v[tid - 39];
    }
    if (tid < 2) sglb[tid] = d_s1[NN * 2 + tid];
    __syncthreads();
    int w = tid >> 5, lane = tid & 31;
    int vb = blockIdx.x * 32 + w * 4;
    int p0 = lane * 2, p1 = lane * 2 + 1;

    // Phase A: layernorm for 4 nodes
    #pragma unroll
    for (int q = 0; q < 4; q++) {
        int v = vb + q;
        float2 p = ((const float2*)tf)[v * 32 + lane];
        float st = 0, sst = 0, sv = 0, ssv = 0;
        if (p0 < 39) { st += p.x; sst += p.x * p.x; } else { sv += p.x; ssv += p.x * p.x; }
        if (p1 < 39) { st += p.y; sst += p.y * p.y; } else { sv += p.y; ssv += p.y * p.y; }
        #pragma unroll
        for (int o = 16; o; o >>= 1) {
            st  += __shfl_xor_sync(0xffffffffu, st, o);
            sst += __shfl_xor_sync(0xffffffffu, sst, o);
            sv  += __shfl_xor_sync(0xffffffffu, sv, o);
            ssv += __shfl_xor_sync(0xffffffffu, ssv, o);
        }
        float mt = st * (1.f / 39.f), vt = sst * (1.f / 39.f) - mt * mt;
        float mv = sv * (1.f / 25.f), vv = ssv * (1.f / 25.f) - mv * mv;
        float rt = rsqrtf(vt + 1e-5f), rv = rsqrtf(vv + 1e-5f);
        float n0 = (p0 < 39) ? (p.x - mt) * rt : (p.x - mv) * rv;
        float n1 = (p1 < 39) ? (p.y - mt) * rt : (p.y - mv) * rv;
        snorm[w * 4 + q][p0] = n0 * sgp[p0] + sbp[p0];
        snorm[w * 4 + q][p1] = n1 * sgp[p1] + sbp[p1];
    }
    __syncwarp();

    // Phase B: GEMM, 4 nodes per warp, packed f32x2
    int j0 = lane * 4;
    unsigned long long a01[4], a23[4];
    {
        unsigned long long c01 = f2pk(sc[j0], sc[j0 + 1]);
        unsigned long long c23 = f2pk(sc[j0 + 2], sc[j0 + 3]);
        #pragma unroll
        for (int q = 0; q < 4; q++) { a01[q] = c01; a23[q] = c23; }
    }
    const float* sn = &snorm[w * 4][0];
    #pragma unroll 4
    for (int i = 0; i < 64; i++) {
        float4 m4 = *(const float4*)&sM[i * 128 + j0];
        unsigned long long m01 = f2pk(m4.x, m4.y);
        unsigned long long m23 = f2pk(m4.z, m4.w);
        #pragma unroll
        for (int q = 0; q < 4; q++) {
            float x = sn[q * 64 + i];
            unsigned long long xq = f2pk(x, x);
            f2fma(a01[q], xq, m01);
            f2fma(a23[q], xq, m23);
        }
    }

    // Phase C: epilogue per node
    float4 as4 = *(const float4*)&sas[j0];
    float4 ad4 = *(const float4*)&sad[j0];
    float4 xg4 = *(const float4*)&sxg[j0];
    int h = lane >> 4;
    float s1g = sglb[h];
    #pragma unroll
    for (int q = 0; q < 4; q++) {
        int v = vb + q;
        float2 lo = f2up(a01[q]), hi = f2up(a23[q]);
        float4 acc = make_float4(lo.x, lo.y, hi.x, hi.y);
        *(float4*)&d_xh1[v * 128 + j0] = acc;
        float ps = acc.x * as4.x + acc.y * as4.y + acc.z * as4.z + acc.w * as4.w;
        float pd = acc.x * ad4.x + acc.y * ad4.y + acc.z * ad4.z + acc.w * ad4.w;
        #pragma unroll
        for (int o = 8; o; o >>= 1) {
            ps += __shfl_xor_sync(0xffffffffu, ps, o);
            pd += __shfl_xor_sync(0xffffffffu, pd, o);
        }
        float exg = expf(lrelu(s1g + pd));
        float exs = expf(lrelu(ps + pd));
        float4 ai;
        ai.x = exg * xg4.x + exs * acc.x;
        ai.y = exg * xg4.y + exs * acc.y;
        ai.z = exg * xg4.z + exs * acc.z;
        ai.w = exg * xg4.w + exs * acc.w;
        *(float4*)&d_acc1[v * 128 + j0] = ai;
        if (lane == 0)  { d_s1[v * 2]     = ps; d_d1[v * 2]     = pd; d_den1[v * 2]     = exg + exs; }
        if (lane == 16) { d_s1[v * 2 + 1] = ps; d_d1[v * 2 + 1] = pd; d_den1[v * 2 + 1] = exg + exs; }
    }
}

// ---------------- GAT1 random edges: den + numerator (warp per edge) ----------------
__global__ __launch_bounds__(256) void k_e2acc(const int* __restrict__ ei) {
    int w = (blockIdx.x * 256 + threadIdx.x) >> 5;
    int lane = threadIdx.x & 31;
    if (w >= EE) return;
    int s = ei[w], d = ei[EE + w];
    float2 sv = *(const float2*)&d_s1[s * 2];
    float2 dv = *(const float2*)&d_d1[d * 2];
    float ex0 = expf(lrelu(sv.x + dv.x));
    float ex1 = expf(lrelu(sv.y + dv.y));
    if (lane == 0) {
        atomicAdd(&d_den1[d * 2],     ex0);
        atomicAdd(&d_den1[d * 2 + 1], ex1);
    }
    int j = lane * 4;
    float wg = (j < 64) ? ex0 : ex1;
    float4 x = *(const float4*)&d_xh1[s * 128 + j];
    float* p = &d_acc1[d * 128 + j];
    asm volatile("red.global.add.v4.f32 [%0], {%1,%2,%3,%4};"
                 :: "l"(p), "f"(wg * x.x), "f"(wg * x.y), "f"(wg * x.z), "f"(wg * x.w)
                 : "memory");
}

// ---------------- GAT1 glb den + numerator: chunked segmented reduction ----------------
__global__ __launch_bounds__(128) void k_glbacc1() {
    int g = blockIdx.x / NCHUNK, c = blockIdx.x % NCHUNK;
    int j = threadIdx.x;
    int h = j >> 6;
    float d1g = d_d1[NN * 2 + h];
    int i0 = g * NPER + c * CHUNK;
    float acc = 0.f, den = 0.f;
    #pragma unroll 5
    for (int i = i0; i < i0 + CHUNK; i++) {
        float ex = expf(lrelu(d_s1[i * 2 + h] + d1g));
        acc += ex * d_xh1[i * 128 + j];
        den += ex;
    }
    if (c == 0) { // self-loop (glb->glb)
        float exs = expf(lrelu(d_s1[NN * 2 + h] + d1g));
        acc += exs * d_xh1[NN * 128 + j];
        den += exs;
    }
    atomicAdd(&d_acc1[(NN + g) * 128 + j], acc);
    if (j == 0 || j == 64) atomicAdd(&d_den1[(NN + g) * 2 + h], den);
}

// ---------------- finish GAT1 + GAT2 projection (32 nodes/block) ----------------
__global__ __launch_bounds__(256) void k_node2(const float* __restrict__ W2, const float* __restrict__ b1,
                                               const float* __restrict__ a2s, const float* __restrict__ a2d)
{
    __shared__ float sW[128 * 64];   // 32KB
    __shared__ float sh[32][128];    // 16KB
    int tid = threadIdx.x;
    for (int t = tid; t < 128 * 64; t += 256) sW[t] = W2[t];
    __syncthreads();
    int w = tid >> 5, lane = tid & 31;
    int vb = blockIdx.x * 32 + w * 4;
    int j0 = lane * 4;
    int h = (j0 >= 64);
    float4 b14 = *(const float4*)&b1[j0];

    #pragma unroll
    for (int q = 0; q < 4; q++) {
        int v = vb + q;
        float2 den2r = *(const float2*)&d_den1[v * 2];
        float r = 1.f / ((h ? den2r.y : den2r.x) + 1e-16f);
        float4 num = *(const float4*)&d_acc1[v * 128 + j0];
        sh[w * 4 + q][j0 + 0] = fmaxf(num.x * r + b14.x, 0.f);
        sh[w * 4 + q][j0 + 1] = fmaxf(num.y * r + b14.y, 0.f);
        sh[w * 4 + q][j0 + 2] = fmaxf(num.z * r + b14.z, 0.f);
        sh[w * 4 + q][j0 + 3] = fmaxf(num.w * r + b14.w, 0.f);
    }
    __syncwarp();

    int c0 = lane * 2;
    unsigned long long accq[4];
    #pragma unroll
    for (int q = 0; q < 4; q++) accq[q] = f2pk(0.f, 0.f);
    const float* shp = &sh[w * 4][0];
    #pragma unroll 4
    for (int k = 0; k < 128; k++) {
        float2 mw2 = *(const float2*)&sW[k * 64 + c0];
        unsigned long long mw = f2pk(mw2.x, mw2.y);
        #pragma unroll
        for (int q = 0; q < 4; q++) {
            float x = shp[q * 128 + k];
            f2fma(accq[q], f2pk(x, x), mw);
        }
    }

    float2 as2 = *(const float2*)&a2s[c0];
    float2 ad2 = *(const float2*)&a2d[c0];
    #pragma unroll
    for (int q = 0; q < 4; q++) {
        int v = vb + q;
        float2 o = f2up(accq[q]);
        *(float2*)&d_xh2[v * 64 + c0] = o;
        float ps = o.x * as2.x + o.y * as2.y;
        float pd = o.x * ad2.x + o.y * ad2.y;
        #pragma unroll
        for (int of = 16; of; of >>= 1) {
            ps += __shfl_xor_sync(0xffffffffu, ps, of);
            pd += __shfl_xor_sync(0xffffffffu, pd, of);
        }
        if (lane == 0) { d_s2[v] = ps; d_d2[v] = pd; d_den2[v] = 0.f; }
    }
}

// ---------------- GAT2 den: det part (tree) + random edges, atomics ----------------
__global__ void k_den2(const int* __restrict__ ei) {
    int i = blockIdx.x * blockDim.x + threadIdx.x;
    if (i < NN) {
        int g = i / NPER;
        float d2i = d_d2[i];
        float v = expf(lrelu(d_s2[NN + g] + d2i)) + expf(lrelu(d_s2[i] + d2i));
        atomicAdd(&d_den2[i], v);
    } else if (i < NN + EE) {
        int e = i - NN;
        int s = ei[e], d = ei[EE + e];
        atomicAdd(&d_den2[d], expf(lrelu(d_s2[s] + d_d2[d])));
    }
}

// ---------------- GAT2 glb den + numerator ----------------
__global__ __launch_bounds__(64) void k_glbacc2() {
    int g = blockIdx.x / NCHUNK, c = blockIdx.x % NCHUNK;
    int j = threadIdx.x;
    float d2g = d_d2[NN + g];
    int i0 = g * NPER + c * CHUNK;
    float acc = 0.f, den = 0.f;
    #pragma unroll 5
    for (int i = i0; i < i0 + CHUNK; i++) {
        float ex = expf(lrelu(d_s2[i] + d2g));
        acc += ex * d_xh2[i * 64 + j];
        den += ex;
    }
    if (c == 0) { // self-loop
        float exs = expf(lrelu(d_s2[NN + g] + d2g));
        acc += exs * d_xh2[(NN + g) * 64 + j];
        den += exs;
    }
    atomicAdd(&d_acc2[g * 64 + j], acc);
    if (j == 0) atomicAdd(&d_den2[NN + g], den);
}

// ---------------- emit src/dst + final attention weights ----------------
__global__ void k_edges(const int* __restrict__ ei, float* __restrict__ out) {
    int e = blockIdx.x * blockDim.x + threadIdx.x;
    if (e >= ETOT) return;
    int s, d; edge_sd(e, ei, s, d);
    out[2048 + e] = (float)s;
    out[2048 + ETOT + e] = (float)d;
    float ex = expf(lrelu(d_s2[s] + d_d2[d]));
    out[2048 + 2 * ETOT + e] = ex / (d_den2[d] + 1e-16f);
}

// ---------------- finalize tree_glb ----------------
__global__ void k_fin(const float* __restrict__ b2, float* __restrict__ out) {
    int t = blockIdx.x * blockDim.x + threadIdx.x;
    if (t >= BB * 64) return;
    int g = t >> 6, j = t & 63;
    out[t] = d_acc2[t] / (d_den2[NN + g] + 1e-16f) + b2[j];
}

// ---------------- launch ----------------
extern "C" void kernel_launch(void* const* d_in, const int* in_sizes, int n_in,
                              void* d_out, int out_size) {
    const float* tree_feature = (const float*)d_in[0];
    const int*   edge_index   = (const int*)d_in[1];
    const float* ln_tree_g  = (const float*)d_in[4];
    const float* ln_tree_b  = (const float*)d_in[5];
    const float* lin_tree_W = (const float*)d_in[6];
    const float* lin_tree_b = (const float*)d_in[7];
    const float* ln_var_g   = (const float*)d_in[8];
    const float* ln_var_b   = (const float*)d_in[9];
    const float* lin_var_W  = (const float*)d_in[10];
    const float* lin_var_b  = (const float*)d_in[11];
    const float* glb_W      = (const float*)d_in[12];
    const float* glb_b      = (const float*)d_in[13];
    const float* glbNode    = (const float*)d_in[14];
    const float* gat1_W     = (const float*)d_in[15];
    const float* gat1_as    = (const float*)d_in[16];
    const float* gat1_ad    = (const float*)d_in[17];
    const float* gat1_b     = (const float*)d_in[18];
    const float* gat2_W     = (const float*)d_in[19];
    const float* gat2_as    = (const float*)d_in[20];
    const float* gat2_ad    = (const float*)d_in[21];
    const float* gat2_b     = (const float*)d_in[22];
    float* out = (float*)d_out;

    k_pre<<<1, 128>>>(lin_tree_W, lin_tree_b, lin_var_W, lin_var_b,
                      glb_W, glb_b, glbNode, gat1_W, gat1_as, gat1_ad);
    k_node1<<<NN / 32, 256>>>(tree_feature, ln_tree_g, ln_tree_b,
                              ln_var_g, ln_var_b, gat1_as, gat1_ad);
    k_e2acc<<<EE / 8, 256>>>(edge_index);
    k_glbacc1<<<BB * NCHUNK, 128>>>();
    k_node2<<<NTOT / 32, 256>>>(gat2_W, gat1_b, gat2_as, gat2_ad);
    k_den2<<<(NN + EE + 255) / 256, 256>>>(edge_index);
    k_glbacc2<<<BB * NCHUNK, 64>>>();
    k_edges<<<(ETOT + 255) / 256, 256>>>(edge_index, out);
    k_fin<<<8, 256>>>(gat2_b, out);
}

// round 4
// speedup vs baseline: 4.3746x; 1.1279x over previous
#include <cuda_runtime.h>
#include <cuda_bf16.h>
#include <math.h>

#define NN   100000
#define BB   32
#define NPER 3125
#define EE   200000
#define NTOT 100032
#define ETOT 500032
#define CHUNK 25
#define NCHUNK 125
#define NBDEN ((NN + EE + 255) / 256)
#define EBLK ((ETOT + 255) / 256)

// ---------------- scratch ----------------
__device__ float d_T[64 * 64];
__device__ float d_bx[64];
__device__ float d_M[64 * 128];
__device__ float d_c[128];
__device__ float d_xh1[NTOT * 128];
__device__ float d_s1[NTOT * 2];
__device__ float d_d1[NTOT * 2];
__device__ float d_den1[NTOT * 2];
__device__ float d_acc1[NTOT * 128];
__device__ float d_xh2[NTOT * 64];
__device__ float d_s2[NTOT];
__device__ float d_d2[NTOT];
__device__ float d_den2[NTOT];
__device__ float d_acc2[BB * 64];

// ---------------- helpers ----------------
__device__ __forceinline__ float lrelu(float x) { return x > 0.f ? x : 0.2f * x; }

__device__ __forceinline__ void edge_sd(int e, const int* __restrict__ ei, int& s, int& d) {
    if (e < EE)               { s = ei[e]; d = ei[EE + e]; }
    else if (e < EE + NN)     { int i = e - EE;          d = i; s = NN + i / NPER; }
    else if (e < EE + 2 * NN) { int i = e - EE - NN;     s = i; d = NN + i / NPER; }
    else                      { int i = e - EE - 2 * NN; s = i; d = i; }
}

__device__ __forceinline__ unsigned long long f2pk(float lo, float hi) {
    unsigned long long r;
    asm("mov.b64 %0, {%1, %2};" : "=l"(r) : "f"(lo), "f"(hi));
    return r;
}
__device__ __forceinline__ void f2fma(unsigned long long& d, unsigned long long a, unsigned long long b) {
    asm("fma.rn.f32x2 %0, %1, %2, %0;" : "+l"(d) : "l"(a), "l"(b));
}
__device__ __forceinline__ float2 f2up(unsigned long long v) {
    float2 r;
    asm("mov.b64 {%0, %1}, %2;" : "=f"(r.x), "=f"(r.y) : "l"(v));
    return r;
}

// ---------------- preA: T = lin_W @ glb_W halves, bias vector ----------------
__global__ void k_preA(const float* __restrict__ ltW, const float* __restrict__ ltb,
                       const float* __restrict__ lvW, const float* __restrict__ lvb,
                       const float* __restrict__ glbW, const float* __restrict__ glbb) {
    int idx = blockIdx.x * 256 + threadIdx.x;
    if (idx < 4096) {
        int i = idx >> 6, m = idx & 63;
        float a = 0.f;
        if (i < 39) {
            for (int k = 0; k < 64; k++) a += ltW[i * 64 + k] * glbW[(64 + k) * 64 + m];
        } else {
            int iv = i - 39;
            for (int k = 0; k < 64; k++) a += lvW[iv * 64 + k] * glbW[k * 64 + m];
        }
        d_T[idx] = a;
    } else if (idx < 4160) {
        int m = idx - 4096;
        float a = glbb[m];
        for (int k = 0; k < 64; k++)
            a += lvb[k] * glbW[k * 64 + m] + ltb[k] * glbW[(64 + k) * 64 + m];
        d_bx[m] = a;
    }
}

// ---------------- preB: M = T @ gat1_W, c, glb features + inits ----------------
__global__ __launch_bounds__(256) void k_preB(const float* __restrict__ glbNode,
                                              const float* __restrict__ gat1_W,
                                              const float* __restrict__ a1s,
                                              const float* __restrict__ a1d) {
    int b = blockIdx.x, tid = threadIdx.x;
    if (b < 32) {
        __shared__ float sT[2 * 64];
        if (tid < 128) sT[tid] = d_T[b * 128 + tid];
        __syncthreads();
        int r = tid >> 7, j = tid & 127;
        float a = 0.f;
        #pragma unroll 8
        for (int k = 0; k < 64; k++) a += sT[r * 64 + k] * gat1_W[k * 128 + j];
        d_M[(b * 2 + r) * 128 + j] = a;
    } else {
        __shared__ float sxg[128];
        __shared__ float sc4[4];
        __shared__ float sex[2];
        if (tid < 128) {
            float xg = 0.f, cj = 0.f;
            for (int m = 0; m < 64; m++) {
                float w = gat1_W[m * 128 + tid];
                xg += glbNode[m] * w;
                cj += d_bx[m] * w;
            }
            sxg[tid] = xg;
            d_c[tid] = cj;
        }
        __syncthreads();
        if (tid == 0) {
            float s0 = 0, s1 = 0, dd0 = 0, dd1 = 0;
            for (int c = 0; c < 64; c++) {
                s0 += sxg[c] * a1s[c];           dd0 += sxg[c] * a1d[c];
                s1 += sxg[64 + c] * a1s[64 + c]; dd1 += sxg[64 + c] * a1d[64 + c];
            }
            sc4[0] = s0; sc4[1] = s1; sc4[2] = dd0; sc4[3] = dd1;
            sex[0] = expf(lrelu(s0 + dd0));
            sex[1] = expf(lrelu(s1 + dd1));
        }
        __syncthreads();
        if (tid < 128) {
            int h = tid >> 6;
            float xg = sxg[tid];
            float ai = sex[h] * xg;
            for (int g = 0; g < BB; g++) {
                d_xh1[(NN + g) * 128 + tid] = xg;
                d_acc1[(NN + g) * 128 + tid] = ai;   // self-loop of glb node
            }
        }
        if (tid < 64) d_den1[NN * 2 + tid] = sex[tid & 1];
        if (tid < BB) {
            d_den2[NN + tid] = 0.f;
            d_s1[(NN + tid) * 2]     = sc4[0];
            d_s1[(NN + tid) * 2 + 1] = sc4[1];
            d_d1[(NN + tid) * 2]     = sc4[2];
            d_d1[(NN + tid) * 2 + 1] = sc4[3];
        }
        for (int t = tid; t < BB * 64; t += 256) d_acc2[t] = 0.f;
    }
}

// ---------------- fused LN + GEMM + det-edge init + glb-agg partials ----------------
__global__ __launch_bounds__(256) void k_node1(const float* __restrict__ tf,
                                               const float* __restrict__ g_t, const float* __restrict__ b_t,
                                               const float* __restrict__ g_v, const float* __restrict__ b_v,
                                               const float* __restrict__ a1s, const float* __restrict__ a1d)
{
    __shared__ float sM[64 * 128];
    __shared__ float sc[128], sas[128], sad[128], sxg[128];
    __shared__ float sgp[64], sbp[64];
    __shared__ float sgs[2], sgd[2];
    __shared__ float snorm[32][64];
    __shared__ float sacc[2][128];
    __shared__ float sden[2][2];
    int tid = threadIdx.x;
    for (int t = tid; t < 64 * 128; t += 256) sM[t] = d_M[t];
    if (tid < 128) {
        sc[tid] = d_c[tid]; sas[tid] = a1s[tid]; sad[tid] = a1d[tid];
        sxg[tid] = d_xh1[NN * 128 + tid];
    }
    if (tid < 64) {
        sgp[tid] = (tid < 39) ? g_t[tid] : g_v[tid - 39];
        sbp[tid] = (tid < 39) ? b_t[tid] : b_v[tid - 39];
    }
    if (tid < 2) { sgs[tid] = d_s1[NN * 2 + tid]; sgd[tid] = d_d1[NN * 2 + tid]; }
    if (tid < 256) sacc[tid >> 7][tid & 127] = 0.f;
    if (tid < 4) sden[tid >> 1][tid & 1] = 0.f;
    __syncthreads();
    int w = tid >> 5, lane = tid & 31;
    int vb = blockIdx.x * 32 + w * 4;
    int p0 = lane * 2, p1 = lane * 2 + 1;

    // Phase A: layernorm 4 nodes
    #pragma unroll
    for (int q = 0; q < 4; q++) {
        int v = vb + q;
        float2 p = ((const float2*)tf)[v * 32 + lane];
        float st = 0, sst = 0, sv = 0, ssv = 0;
        if (p0 < 39) { st += p.x; sst += p.x * p.x; } else { sv += p.x; ssv += p.x * p.x; }
        if (p1 < 39) { st += p.y; sst += p.y * p.y; } else { sv += p.y; ssv += p.y * p.y; }
        #pragma unroll
        for (int o = 16; o; o >>= 1) {
            st  += __shfl_xor_sync(0xffffffffu, st, o);
            sst += __shfl_xor_sync(0xffffffffu, sst, o);
            sv  += __shfl_xor_sync(0xffffffffu, sv, o);
            ssv += __shfl_xor_sync(0xffffffffu, ssv, o);
        }
        float mt = st * (1.f / 39.f), vt = sst * (1.f / 39.f) - mt * mt;
        float mv = sv * (1.f / 25.f), vv = ssv * (1.f / 25.f) - mv * mv;
        float rt = rsqrtf(vt + 1e-5f), rv = rsqrtf(vv + 1e-5f);
        float n0 = (p0 < 39) ? (p.x - mt) * rt : (p.x - mv) * rv;
        float n1 = (p1 < 39) ? (p.y - mt) * rt : (p.y - mv) * rv;
        snorm[w * 4 + q][p0] = n0 * sgp[p0] + sbp[p0];
        snorm[w * 4 + q][p1] = n1 * sgp[p1] + sbp[p1];
    }
    __syncwarp();

    // Phase B: GEMM, packed f32x2
    int j0 = lane * 4;
    unsigned long long a01[4], a23[4];
    {
        unsigned long long c01 = f2pk(sc[j0], sc[j0 + 1]);
        unsigned long long c23 = f2pk(sc[j0 + 2], sc[j0 + 3]);
        #pragma unroll
        for (int q = 0; q < 4; q++) { a01[q] = c01; a23[q] = c23; }
    }
    const float* sn = &snorm[w * 4][0];
    #pragma unroll 4
    for (int i = 0; i < 64; i++) {
        float4 m4 = *(const float4*)&sM[i * 128 + j0];
        unsigned long long m01 = f2pk(m4.x, m4.y);
        unsigned long long m23 = f2pk(m4.z, m4.w);
        #pragma unroll
        for (int q = 0; q < 4; q++) {
            float x = sn[q * 64 + i];
            unsigned long long xq = f2pk(x, x);
            f2fma(a01[q], xq, m01);
            f2fma(a23[q], xq, m23);
        }
    }

    // Phase C: epilogue + glb-agg partials
    float4 as4 = *(const float4*)&sas[j0];
    float4 ad4 = *(const float4*)&sad[j0];
    float4 xg4 = *(const float4*)&sxg[j0];
    int h = lane >> 4;
    float s1g = sgs[h], d1g = sgd[h];
    int g0blk = (blockIdx.x * 32) / NPER;
    bool fast = (vb / NPER) == ((vb + 3) / NPER);
    float4 pac = make_float4(0.f, 0.f, 0.f, 0.f);
    float pden = 0.f;
    #pragma unroll
    for (int q = 0; q < 4; q++) {
        int v = vb + q;
        float2 lo = f2up(a01[q]), hi = f2up(a23[q]);
        float4 acc = make_float4(lo.x, lo.y, hi.x, hi.y);
        *(float4*)&d_xh1[v * 128 + j0] = acc;
        float ps = acc.x * as4.x + acc.y * as4.y + acc.z * as4.z + acc.w * as4.w;
        float pd = acc.x * ad4.x + acc.y * ad4.y + acc.z * ad4.z + acc.w * ad4.w;
        #pragma unroll
        for (int o = 8; o; o >>= 1) {
            ps += __shfl_xor_sync(0xffffffffu, ps, o);
            pd += __shfl_xor_sync(0xffffffffu, pd, o);
        }
        // incoming det edges to v: glb->v and self-loop
        float exg = expf(lrelu(s1g + pd));
        float exs = expf(lrelu(ps + pd));
        float4 ai;
        ai.x = exg * xg4.x + exs * acc.x;
        ai.y = exg * xg4.y + exs * acc.y;
        ai.z = exg * xg4.z + exs * acc.z;
        ai.w = exg * xg4.w + exs * acc.w;
        *(float4*)&d_acc1[v * 128 + j0] = ai;
        if (lane == 0)  { d_s1[v * 2]     = ps; d_d1[v * 2]     = pd; d_den1[v * 2]     = exg + exs; }
        if (lane == 16) { d_s1[v * 2 + 1] = ps; d_d1[v * 2 + 1] = pd; d_den1[v * 2 + 1] = exg + exs; }
        // outgoing det edge v->glb: partial aggregation
        float exv = expf(lrelu(ps + d1g));
        if (fast) {
            pac.x += exv * acc.x; pac.y += exv * acc.y;
            pac.z += exv * acc.z; pac.w += exv * acc.w;
            pden += exv;
        } else {
            int sel = (v / NPER) != g0blk;
            atomicAdd(&sacc[sel][j0 + 0], exv * acc.x);
            atomicAdd(&sacc[sel][j0 + 1], exv * acc.y);
            atomicAdd(&sacc[sel][j0 + 2], exv * acc.z);
            atomicAdd(&sacc[sel][j0 + 3], exv * acc.w);
            if (lane == 0 || lane == 16) atomicAdd(&sden[sel][h], exv);
        }
    }
    if (fast) {
        int sel = (vb / NPER) != g0blk;
        atomicAdd(&sacc[sel][j0 + 0], pac.x);
        atomicAdd(&sacc[sel][j0 + 1], pac.y);
        atomicAdd(&sacc[sel][j0 + 2], pac.z);
        atomicAdd(&sacc[sel][j0 + 3], pac.w);
        if (lane == 0 || lane == 16) atomicAdd(&sden[sel][h], pden);
    }
    __syncthreads();
    int gl = (blockIdx.x * 32 + 31) / NPER;
    if (tid < 128) {
        atomicAdd(&d_acc1[(NN + g0blk) * 128 + tid], sacc[0][tid]);
    } else if (gl != g0blk) {
        atomicAdd(&d_acc1[(NN + gl) * 128 + (tid - 128)], sacc[1][tid - 128]);
    }
    if (tid < 2) atomicAdd(&d_den1[(NN + g0blk) * 2 + tid], sden[0][tid]);
    if (gl != g0blk && (tid == 2 || tid == 3)) atomicAdd(&d_den1[(NN + gl) * 2 + (tid - 2)], sden[1][tid - 2]);
}

// ---------------- GAT1 random edges: den + numerator (warp per edge) ----------------
__global__ __launch_bounds__(256) void k_e2acc(const int* __restrict__ ei) {
    int w = (blockIdx.x * 256 + threadIdx.x) >> 5;
    int lane = threadIdx.x & 31;
    if (w >= EE) return;
    int s = ei[w], d = ei[EE + w];
    float2 sv = *(const float2*)&d_s1[s * 2];
    float2 dv = *(const float2*)&d_d1[d * 2];
    float ex0 = expf(lrelu(sv.x + dv.x));
    float ex1 = expf(lrelu(sv.y + dv.y));
    if (lane == 0) {
        atomicAdd(&d_den1[d * 2],     ex0);
        atomicAdd(&d_den1[d * 2 + 1], ex1);
    }
    int j = lane * 4;
    float wg = (j < 64) ? ex0 : ex1;
    float4 x = *(const float4*)&d_xh1[s * 128 + j];
    float* p = &d_acc1[d * 128 + j];
    asm volatile("red.global.add.v4.f32 [%0], {%1,%2,%3,%4};"
                 :: "l"(p), "f"(wg * x.x), "f"(wg * x.y), "f"(wg * x.z), "f"(wg * x.w)
                 : "memory");
}

// ---------------- finish GAT1 + GAT2 projection (32 nodes/block) ----------------
__global__ __launch_bounds__(256) void k_node2(const float* __restrict__ W2, const float* __restrict__ b1,
                                               const float* __restrict__ a2s, const float* __restrict__ a2d)
{
    __shared__ float sW[128 * 64];
    __shared__ float sh[32][128];
    int tid = threadIdx.x;
    for (int t = tid; t < 128 * 64; t += 256) sW[t] = W2[t];
    __syncthreads();
    int w = tid >> 5, lane = tid & 31;
    int vb = blockIdx.x * 32 + w * 4;
    int j0 = lane * 4;
    int h = (j0 >= 64);
    float4 b14 = *(const float4*)&b1[j0];

    #pragma unroll
    for (int q = 0; q < 4; q++) {
        int v = vb + q;
        float2 den2r = *(const float2*)&d_den1[v * 2];
        float r = 1.f / ((h ? den2r.y : den2r.x) + 1e-16f);
        float4 num = *(const float4*)&d_acc1[v * 128 + j0];
        sh[w * 4 + q][j0 + 0] = fmaxf(num.x * r + b14.x, 0.f);
        sh[w * 4 + q][j0 + 1] = fmaxf(num.y * r + b14.y, 0.f);
        sh[w * 4 + q][j0 + 2] = fmaxf(num.z * r + b14.z, 0.f);
        sh[w * 4 + q][j0 + 3] = fmaxf(num.w * r + b14.w, 0.f);
    }
    __syncwarp();

    int c0 = lane * 2;
    unsigned long long accq[4];
    #pragma unroll
    for (int q = 0; q < 4; q++) accq[q] = f2pk(0.f, 0.f);
    const float* shp = &sh[w * 4][0];
    #pragma unroll 4
    for (int k = 0; k < 128; k++) {
        float2 mw2 = *(const float2*)&sW[k * 64 + c0];
        unsigned long long mw = f2pk(mw2.x, mw2.y);
        #pragma unroll
        for (int q = 0; q < 4; q++) {
            float x = shp[q * 128 + k];
            f2fma(accq[q], f2pk(x, x), mw);
        }
    }

    float2 as2 = *(const float2*)&a2s[c0];
    float2 ad2 = *(const float2*)&a2d[c0];
    #pragma unroll
    for (int q = 0; q < 4; q++) {
        int v = vb + q;
        float2 o = f2up(accq[q]);
        *(float2*)&d_xh2[v * 64 + c0] = o;
        float ps = o.x * as2.x + o.y * as2.y;
        float pd = o.x * ad2.x + o.y * ad2.y;
        #pragma unroll
        for (int of = 16; of; of >>= 1) {
            ps += __shfl_xor_sync(0xffffffffu, ps, of);
            pd += __shfl_xor_sync(0xffffffffu, pd, of);
        }
        if (lane == 0) { d_s2[v] = ps; d_d2[v] = pd; if (v < NN) d_den2[v] = 0.f; }
    }
}

// ---------------- merged: GAT2 den (det+random) + glb den/numerator ----------------
__global__ __launch_bounds__(256) void k_post2(const int* __restrict__ ei) {
    int b = blockIdx.x, tid = threadIdx.x;
    if (b < NBDEN) {
        int i = b * 256 + tid;
        if (i < NN) {
            int g = i / NPER;
            float d2i = d_d2[i];
            atomicAdd(&d_den2[i], expf(lrelu(d_s2[NN + g] + d2i)) + expf(lrelu(d_s2[i] + d2i)));
        } else if (i < NN + EE) {
            int e = i - NN;
            int s = ei[e], d = ei[EE + e];
            atomicAdd(&d_den2[d], expf(lrelu(d_s2[s] + d_d2[d])));
        }
    } else {
        __shared__ float sred[256];
        __shared__ float sdn[4];
        int gb = b - NBDEN;
        int g = gb / NCHUNK, c = gb % NCHUNK;
        int j = tid & 63, r = tid >> 6;
        float d2g = d_d2[NN + g];
        int i0 = g * NPER + c * CHUNK;
        float acc = 0.f, den = 0.f;
        for (int i = i0 + r; i < i0 + CHUNK; i += 4) {
            float ex = expf(lrelu(d_s2[i] + d2g));
            acc += ex * d_xh2[i * 64 + j];
            den += ex;
        }
        if (c == 0 && r == 0) {
            float exs = expf(lrelu(d_s2[NN + g] + d2g));
            acc += exs * d_xh2[(NN + g) * 64 + j];
            den += exs;
        }
        sred[tid] = acc;
        if (j == 0) sdn[r] = den;
        __syncthreads();
        if (r == 0) {
            acc += sred[tid + 64] + sred[tid + 128] + sred[tid + 192];
            atomicAdd(&d_acc2[g * 64 + j], acc);
            if (j == 0) atomicAdd(&d_den2[NN + g], sdn[0] + sdn[1] + sdn[2] + sdn[3]);
        }
    }
}

// ---------------- merged: emit src/dst + att + tree_glb ----------------
__global__ void k_edgesfin(const int* __restrict__ ei, const float* __restrict__ b2,
                           float* __restrict__ out) {
    int b = blockIdx.x;
    if (b < EBLK) {
        int e = b * 256 + threadIdx.x;
        if (e >= ETOT) return;
        int s, d; edge_sd(e, ei, s, d);
        out[2048 + e] = (float)s;
        out[2048 + ETOT + e] = (float)d;
        float ex = expf(lrelu(d_s2[s] + d_d2[d]));
        out[2048 + 2 * ETOT + e] = ex / (d_den2[d] + 1e-16f);
    } else {
        int t = (b - EBLK) * 256 + threadIdx.x;  // 8 blocks cover 2048
        int g = t >> 6, j = t & 63;
        out[t] = d_acc2[t] / (d_den2[NN + g] + 1e-16f) + b2[j];
    }
}

// ---------------- launch ----------------
extern "C" void kernel_launch(void* const* d_in, const int* in_sizes, int n_in,
                              void* d_out, int out_size) {
    const float* tree_feature = (const float*)d_in[0];
    const int*   edge_index   = (const int*)d_in[1];
    const float* ln_tree_g  = (const float*)d_in[4];
    const float* ln_tree_b  = (const float*)d_in[5];
    const float* lin_tree_W = (const float*)d_in[6];
    const float* lin_tree_b = (const float*)d_in[7];
    const float* ln_var_g   = (const float*)d_in[8];
    const float* ln_var_b   = (const float*)d_in[9];
    const float* lin_var_W  = (const float*)d_in[10];
    const float* lin_var_b  = (const float*)d_in[11];
    const float* glb_W      = (const float*)d_in[12];
    const float* glb_b      = (const float*)d_in[13];
    const float* glbNode    = (const float*)d_in[14];
    const float* gat1_W     = (const float*)d_in[15];
    const float* gat1_as    = (const float*)d_in[16];
    const float* gat1_ad    = (const float*)d_in[17];
    const float* gat1_b     = (const float*)d_in[18];
    const float* gat2_W     = (const float*)d_in[19];
    const float* gat2_as    = (const float*)d_in[20];
    const float* gat2_ad    = (const float*)d_in[21];
    const float* gat2_b     = (const float*)d_in[22];
    float* out = (float*)d_out;

    k_preA<<<17, 256>>>(lin_tree_W, lin_tree_b, lin_var_W, lin_var_b, glb_W, glb_b);
    k_preB<<<33, 256>>>(glbNode, gat1_W, gat1_as, gat1_ad);
    k_node1<<<NN / 32, 256>>>(tree_feature, ln_tree_g, ln_tree_b,
                              ln_var_g, ln_var_b, gat1_as, gat1_ad);
    k_e2acc<<<EE / 8, 256>>>(edge_index);
    k_node2<<<NTOT / 32, 256>>>(gat2_W, gat1_b, gat2_as, gat2_ad);
    k_post2<<<NBDEN + BB * NCHUNK, 256>>>(edge_index);
    k_edgesfin<<<EBLK + 8, 256>>>(edge_index, gat2_b, out);
}

// round 5
// speedup vs baseline: 6.4264x; 1.4690x over previous
#include <cuda_runtime.h>
#include <cuda_bf16.h>
#include <math.h>

#define NN   100000
#define BB   32
#define NPER 3125
#define EE   200000
#define NTOT 100032
#define ETOT 500032
#define CHUNK 25
#define NCHUNK 125
#define NBDEN ((NN + EE + 255) / 256)
#define EBLK ((ETOT + 255) / 256)

typedef unsigned long long ull;

// ---------------- scratch ----------------
__device__ float d_T[64 * 64];
__device__ float d_bx[64];
__device__ float d_M[64 * 128];
__device__ float d_c[128];
__device__ float d_xh1[NTOT * 128];
__device__ float d_s1[NTOT * 2];
__device__ float d_d1[NTOT * 2];
__device__ float d_den1[NTOT * 2];
__device__ float d_acc1[NTOT * 128];
__device__ float d_xh2[NTOT * 64];
__device__ float d_s2[NTOT];
__device__ float d_d2[NTOT];
__device__ float d_den2[NTOT];
__device__ float d_acc2[BB * 64];

// ---------------- helpers ----------------
__device__ __forceinline__ float lrelu(float x) { return x > 0.f ? x : 0.2f * x; }

__device__ __forceinline__ void edge_sd(int e, const int* __restrict__ ei, int& s, int& d) {
    if (e < EE)               { s = ei[e]; d = ei[EE + e]; }
    else if (e < EE + NN)     { int i = e - EE;          d = i; s = NN + i / NPER; }
    else if (e < EE + 2 * NN) { int i = e - EE - NN;     s = i; d = NN + i / NPER; }
    else                      { int i = e - EE - 2 * NN; s = i; d = i; }
}

__device__ __forceinline__ ull f2pk(float lo, float hi) {
    ull r;
    asm("mov.b64 %0, {%1, %2};" : "=l"(r) : "f"(lo), "f"(hi));
    return r;
}
__device__ __forceinline__ void f2fma(ull& d, ull a, ull b) {
    asm("fma.rn.f32x2 %0, %1, %2, %0;" : "+l"(d) : "l"(a), "l"(b));
}
__device__ __forceinline__ float2 f2up(ull v) {
    float2 r;
    asm("mov.b64 {%0, %1}, %2;" : "=f"(r.x), "=f"(r.y) : "l"(v));
    return r;
}
__device__ __forceinline__ float f2sum(ull v) {
    float2 r = f2up(v);
    return r.x + r.y;
}

// ---------------- preA: T = lin_W @ glb_W halves, bias vector ----------------
__global__ void k_preA(const float* __restrict__ ltW, const float* __restrict__ ltb,
                       const float* __restrict__ lvW, const float* __restrict__ lvb,
                       const float* __restrict__ glbW, const float* __restrict__ glbb) {
    int idx = blockIdx.x * 256 + threadIdx.x;
    if (idx < 4096) {
        int i = idx >> 6, m = idx & 63;
        float a = 0.f;
        if (i < 39) {
            for (int k = 0; k < 64; k++) a += ltW[i * 64 + k] * glbW[(64 + k) * 64 + m];
        } else {
            int iv = i - 39;
            for (int k = 0; k < 64; k++) a += lvW[iv * 64 + k] * glbW[k * 64 + m];
        }
        d_T[idx] = a;
    } else if (idx < 4160) {
        int m = idx - 4096;
        float a = glbb[m];
        for (int k = 0; k < 64; k++)
            a += lvb[k] * glbW[k * 64 + m] + ltb[k] * glbW[(64 + k) * 64 + m];
        d_bx[m] = a;
    }
}

// ---------------- preB: M = T @ gat1_W, c, glb features + inits ----------------
__global__ __launch_bounds__(256) void k_preB(const float* __restrict__ glbNode,
                                              const float* __restrict__ gat1_W,
                                              const float* __restrict__ a1s,
                                              const float* __restrict__ a1d) {
    int b = blockIdx.x, tid = threadIdx.x;
    if (b < 32) {
        __shared__ float sT[2 * 64];
        if (tid < 128) sT[tid] = d_T[b * 128 + tid];
        __syncthreads();
        int r = tid >> 7, j = tid & 127;
        float a = 0.f;
        #pragma unroll 8
        for (int k = 0; k < 64; k++) a += sT[r * 64 + k] * gat1_W[k * 128 + j];
        d_M[(b * 2 + r) * 128 + j] = a;
    } else {
        __shared__ float sxg[128];
        __shared__ float sc4[4];
        __shared__ float sex[2];
        if (tid < 128) {
            float xg = 0.f, cj = 0.f;
            for (int m = 0; m < 64; m++) {
                float w = gat1_W[m * 128 + tid];
                xg += glbNode[m] * w;
                cj += d_bx[m] * w;
            }
            sxg[tid] = xg;
            d_c[tid] = cj;
        }
        __syncthreads();
        if (tid == 0) {
            float s0 = 0, s1 = 0, dd0 = 0, dd1 = 0;
            for (int c = 0; c < 64; c++) {
                s0 += sxg[c] * a1s[c];           dd0 += sxg[c] * a1d[c];
                s1 += sxg[64 + c] * a1s[64 + c]; dd1 += sxg[64 + c] * a1d[64 + c];
            }
            sc4[0] = s0; sc4[1] = s1; sc4[2] = dd0; sc4[3] = dd1;
            sex[0] = expf(lrelu(s0 + dd0));
            sex[1] = expf(lrelu(s1 + dd1));
        }
        __syncthreads();
        if (tid < 128) {
            int h = tid >> 6;
            float xg = sxg[tid];
            float ai = sex[h] * xg;
            for (int g = 0; g < BB; g++) {
                d_xh1[(NN + g) * 128 + tid] = xg;
                d_acc1[(NN + g) * 128 + tid] = ai;   // self-loop of glb node
            }
        }
        if (tid < 64) d_den1[NN * 2 + tid] = sex[tid & 1];
        if (tid < BB) {
            d_den2[NN + tid] = 0.f;
            d_s1[(NN + tid) * 2]     = sc4[0];
            d_s1[(NN + tid) * 2 + 1] = sc4[1];
            d_d1[(NN + tid) * 2]     = sc4[2];
            d_d1[(NN + tid) * 2 + 1] = sc4[3];
        }
        for (int t = tid; t < BB * 64; t += 256) d_acc2[t] = 0.f;
    }
}

// ---------------- fused LN + GEMM (k-pair packed f32x2) + det-edge init + glb partials ----------------
__global__ __launch_bounds__(256) void k_node1(const float* __restrict__ tf,
                                               const float* __restrict__ g_t, const float* __restrict__ b_t,
                                               const float* __restrict__ g_v, const float* __restrict__ b_v,
                                               const float* __restrict__ a1s, const float* __restrict__ a1d)
{
    __shared__ __align__(16) ull sMt[32 * 128];   // 32KB: pair (M[2i2][j], M[2i2+1][j])
    __shared__ __align__(16) ull snp[32][32];     // 8KB: [node][i2] = (x_{2i2}, x_{2i2+1})
    __shared__ float sc[128], sas[128], sad[128], sxg[128];
    __shared__ float sgp[64], sbp[64];
    __shared__ float sgs[2], sgd[2];
    __shared__ float sacc[2][128];
    __shared__ float sden[2][2];
    int tid = threadIdx.x;
    // pack M transposed pairs: 4096 entries, 16 iters/thread
    for (int t = tid; t < 32 * 128; t += 256) {
        int i2 = t >> 7, j = t & 127;
        sMt[t] = f2pk(d_M[(2 * i2) * 128 + j], d_M[(2 * i2 + 1) * 128 + j]);
    }
    if (tid < 128) {
        sc[tid] = d_c[tid]; sas[tid] = a1s[tid]; sad[tid] = a1d[tid];
        sxg[tid] = d_xh1[NN * 128 + tid];
    }
    if (tid < 64) {
        sgp[tid] = (tid < 39) ? g_t[tid] : g_v[tid - 39];
        sbp[tid] = (tid < 39) ? b_t[tid] : b_v[tid - 39];
    }
    if (tid < 2) { sgs[tid] = d_s1[NN * 2 + tid]; sgd[tid] = d_d1[NN * 2 + tid]; }
    sacc[tid >> 7][tid & 127] = 0.f;
    if (tid < 4) sden[tid >> 1][tid & 1] = 0.f;
    __syncthreads();
    int w = tid >> 5, lane = tid & 31;
    int vb = blockIdx.x * 32 + w * 4;
    int p0 = lane * 2, p1 = lane * 2 + 1;

    // Phase A: layernorm 4 nodes; (p0,p1) consecutive -> directly a k-pair
    #pragma unroll
    for (int q = 0; q < 4; q++) {
        int v = vb + q;
        float2 p = ((const float2*)tf)[v * 32 + lane];
        float st = 0, sst = 0, sv = 0, ssv = 0;
        if (p0 < 39) { st += p.x; sst += p.x * p.x; } else { sv += p.x; ssv += p.x * p.x; }
        if (p1 < 39) { st += p.y; sst += p.y * p.y; } else { sv += p.y; ssv += p.y * p.y; }
        #pragma unroll
        for (int o = 16; o; o >>= 1) {
            st  += __shfl_xor_sync(0xffffffffu, st, o);
            sst += __shfl_xor_sync(0xffffffffu, sst, o);
            sv  += __shfl_xor_sync(0xffffffffu, sv, o);
            ssv += __shfl_xor_sync(0xffffffffu, ssv, o);
        }
        float mt = st * (1.f / 39.f), vt = sst * (1.f / 39.f) - mt * mt;
        float mv = sv * (1.f / 25.f), vv = ssv * (1.f / 25.f) - mv * mv;
        float rt = rsqrtf(vt + 1e-5f), rv = rsqrtf(vv + 1e-5f);
        float n0 = (p0 < 39) ? (p.x - mt) * rt : (p.x - mv) * rv;
        float n1 = (p1 < 39) ? (p.y - mt) * rt : (p.y - mv) * rv;
        n0 = n0 * sgp[p0] + sbp[p0];
        n1 = n1 * sgp[p1] + sbp[p1];
        snp[w * 4 + q][lane] = f2pk(n0, n1);
    }
    __syncwarp();

    // Phase B: GEMM, k-pair packed: acc pair = (even-k partial, odd-k partial)
    int j0 = lane * 4;
    ull acc[4][4];
    #pragma unroll
    for (int q = 0; q < 4; q++)
        #pragma unroll
        for (int c = 0; c < 4; c++) acc[q][c] = 0ull;
    #pragma unroll 4
    for (int i2 = 0; i2 < 32; i2++) {
        ulonglong2 mA = *(const ulonglong2*)&sMt[i2 * 128 + j0];
        ulonglong2 mB = *(const ulonglong2*)&sMt[i2 * 128 + j0 + 2];
        #pragma unroll
        for (int q = 0; q < 4; q++) {
            ull xq = snp[w * 4 + q][i2];
            f2fma(acc[q][0], xq, mA.x);
            f2fma(acc[q][1], xq, mA.y);
            f2fma(acc[q][2], xq, mB.x);
            f2fma(acc[q][3], xq, mB.y);
        }
    }

    // Phase C: epilogue + glb-agg partials
    float4 as4 = *(const float4*)&sas[j0];
    float4 ad4 = *(const float4*)&sad[j0];
    float4 xg4 = *(const float4*)&sxg[j0];
    float4 c4  = *(const float4*)&sc[j0];
    int h = lane >> 4;
    float s1g = sgs[h], d1g = sgd[h];
    int g0blk = (blockIdx.x * 32) / NPER;
    bool fast = (vb / NPER) == ((vb + 3) / NPER);
    float4 pac = make_float4(0.f, 0.f, 0.f, 0.f);
    float pden = 0.f;
    #pragma unroll
    for (int q = 0; q < 4; q++) {
        int v = vb + q;
        float4 a;
        a.x = f2sum(acc[q][0]) + c4.x;
        a.y = f2sum(acc[q][1]) + c4.y;
        a.z = f2sum(acc[q][2]) + c4.z;
        a.w = f2sum(acc[q][3]) + c4.w;
        *(float4*)&d_xh1[v * 128 + j0] = a;
        float ps = a.x * as4.x + a.y * as4.y + a.z * as4.z + a.w * as4.w;
        float pd = a.x * ad4.x + a.y * ad4.y + a.z * ad4.z + a.w * ad4.w;
        #pragma unroll
        for (int o = 8; o; o >>= 1) {
            ps += __shfl_xor_sync(0xffffffffu, ps, o);
            pd += __shfl_xor_sync(0xffffffffu, pd, o);
        }
        float exg = expf(lrelu(s1g + pd));
        float exs = expf(lrelu(ps + pd));
        float4 ai;
        ai.x = exg * xg4.x + exs * a.x;
        ai.y = exg * xg4.y + exs * a.y;
        ai.z = exg * xg4.z + exs * a.z;
        ai.w = exg * xg4.w + exs * a.w;
        *(float4*)&d_acc1[v * 128 + j0] = ai;
        if (lane == 0)  { d_s1[v * 2]     = ps; d_d1[v * 2]     = pd; d_den1[v * 2]     = exg + exs; }
        if (lane == 16) { d_s1[v * 2 + 1] = ps; d_d1[v * 2 + 1] = pd; d_den1[v * 2 + 1] = exg + exs; }
        float exv = expf(lrelu(ps + d1g));
        if (fast) {
            pac.x += exv * a.x; pac.y += exv * a.y;
            pac.z += exv * a.z; pac.w += exv * a.w;
            pden += exv;
        } else {
            int sel = (v / NPER) != g0blk;
            atomicAdd(&sacc[sel][j0 + 0], exv * a.x);
            atomicAdd(&sacc[sel][j0 + 1], exv * a.y);
            atomicAdd(&sacc[sel][j0 + 2], exv * a.z);
            atomicAdd(&sacc[sel][j0 + 3], exv * a.w);
            if (lane == 0 || lane == 16) atomicAdd(&sden[sel][h], exv);
        }
    }
    if (fast) {
        int sel = (vb / NPER) != g0blk;
        atomicAdd(&sacc[sel][j0 + 0], pac.x);
        atomicAdd(&sacc[sel][j0 + 1], pac.y);
        atomicAdd(&sacc[sel][j0 + 2], pac.z);
        atomicAdd(&sacc[sel][j0 + 3], pac.w);
        if (lane == 0 || lane == 16) atomicAdd(&sden[sel][h], pden);
    }
    __syncthreads();
    int gl = (blockIdx.x * 32 + 31) / NPER;
    if (tid < 128) {
        atomicAdd(&d_acc1[(NN + g0blk) * 128 + tid], sacc[0][tid]);
    } else if (gl != g0blk) {
        atomicAdd(&d_acc1[(NN + gl) * 128 + (tid - 128)], sacc[1][tid - 128]);
    }
    if (tid < 2) atomicAdd(&d_den1[(NN + g0blk) * 2 + tid], sden[0][tid]);
    if (gl != g0blk && (tid == 2 || tid == 3)) atomicAdd(&d_den1[(NN + gl) * 2 + (tid - 2)], sden[1][tid - 2]);
}

// ---------------- GAT1 random edges: 2 edges per warp ----------------
__global__ __launch_bounds__(256) void k_e2acc(const int* __restrict__ ei) {
    int wp = (blockIdx.x * 256 + threadIdx.x) >> 5;
    int e0 = wp * 2;
    if (e0 >= EE) return;
    int lane = threadIdx.x & 31;
    int s0 = __ldg(&ei[e0]),     d0 = __ldg(&ei[EE + e0]);
    int s1 = __ldg(&ei[e0 + 1]), d1 = __ldg(&ei[EE + e0 + 1]);
    int j = lane * 4;
    float4 x0 = *(const float4*)&d_xh1[s0 * 128 + j];
    float4 x1 = *(const float4*)&d_xh1[s1 * 128 + j];
    float2 sv0 = *(const float2*)&d_s1[s0 * 2];
    float2 dv0 = *(const float2*)&d_d1[d0 * 2];
    float2 sv1 = *(const float2*)&d_s1[s1 * 2];
    float2 dv1 = *(const float2*)&d_d1[d1 * 2];
    float ex00 = expf(lrelu(sv0.x + dv0.x));
    float ex01 = expf(lrelu(sv0.y + dv0.y));
    float ex10 = expf(lrelu(sv1.x + dv1.x));
    float ex11 = expf(lrelu(sv1.y + dv1.y));
    if (lane == 0)
        asm volatile("red.global.add.v2.f32 [%0], {%1,%2};"
                     :: "l"(&d_den1[d0 * 2]), "f"(ex00), "f"(ex01) : "memory");
    if (lane == 16)
        asm volatile("red.global.add.v2.f32 [%0], {%1,%2};"
                     :: "l"(&d_den1[d1 * 2]), "f"(ex10), "f"(ex11) : "memory");
    float wg0 = (j < 64) ? ex00 : ex01;
    float wg1 = (j < 64) ? ex10 : ex11;
    asm volatile("red.global.add.v4.f32 [%0], {%1,%2,%3,%4};"
                 :: "l"(&d_acc1[d0 * 128 + j]),
                    "f"(wg0 * x0.x), "f"(wg0 * x0.y), "f"(wg0 * x0.z), "f"(wg0 * x0.w)
                 : "memory");
    asm volatile("red.global.add.v4.f32 [%0], {%1,%2,%3,%4};"
                 :: "l"(&d_acc1[d1 * 128 + j]),
                    "f"(wg1 * x1.x), "f"(wg1 * x1.y), "f"(wg1 * x1.z), "f"(wg1 * x1.w)
                 : "memory");
}

// ---------------- finish GAT1 + GAT2 projection (k-pair packed) ----------------
__global__ __launch_bounds__(256) void k_node2(const float* __restrict__ W2, const float* __restrict__ b1,
                                               const float* __restrict__ a2s, const float* __restrict__ a2d)
{
    __shared__ __align__(16) ull sWt[64 * 64];   // 32KB: pair (W[2k2][c], W[2k2+1][c])
    __shared__ __align__(16) ull shp[32][64];    // 16KB: [node][k2] = (h_{2k2}, h_{2k2+1})
    int tid = threadIdx.x;
    for (int t = tid; t < 64 * 64; t += 256) {
        int k2 = t >> 6, c = t & 63;
        sWt[t] = f2pk(W2[(2 * k2) * 64 + c], W2[(2 * k2 + 1) * 64 + c]);
    }
    __syncthreads();
    int w = tid >> 5, lane = tid & 31;
    int vb = blockIdx.x * 32 + w * 4;
    int j0 = lane * 4;
    int h = (j0 >= 64);
    float4 b14 = *(const float4*)&b1[j0];

    #pragma unroll
    for (int q = 0; q < 4; q++) {
        int v = vb + q;
        float2 den2r = *(const float2*)&d_den1[v * 2];
        float r = 1.f / ((h ? den2r.y : den2r.x) + 1e-16f);
        float4 num = *(const float4*)&d_acc1[v * 128 + j0];
        float h0 = fmaxf(num.x * r + b14.x, 0.f);
        float h1 = fmaxf(num.y * r + b14.y, 0.f);
        float h2 = fmaxf(num.z * r + b14.z, 0.f);
        float h3 = fmaxf(num.w * r + b14.w, 0.f);
        shp[w * 4 + q][j0 / 2]     = f2pk(h0, h1);
        shp[w * 4 + q][j0 / 2 + 1] = f2pk(h2, h3);
    }
    __syncwarp();

    int c0 = lane * 2;
    ull accq[4][2];
    #pragma unroll
    for (int q = 0; q < 4; q++) { accq[q][0] = 0ull; accq[q][1] = 0ull; }
    #pragma unroll 4
    for (int k2 = 0; k2 < 64; k2++) {
        ulonglong2 mw = *(const ulonglong2*)&sWt[k2 * 64 + c0];
        #pragma unroll
        for (int q = 0; q < 4; q++) {
            ull xp = shp[w * 4 + q][k2];
            f2fma(accq[q][0], xp, mw.x);
            f2fma(accq[q][1], xp, mw.y);
        }
    }

    float2 as2 = *(const float2*)&a2s[c0];
    float2 ad2 = *(const float2*)&a2d[c0];
    #pragma unroll
    for (int q = 0; q < 4; q++) {
        int v = vb + q;
        float2 o;
        o.x = f2sum(accq[q][0]);
        o.y = f2sum(accq[q][1]);
        *(float2*)&d_xh2[v * 64 + c0] = o;
        float ps = o.x * as2.x + o.y * as2.y;
        float pd = o.x * ad2.x + o.y * ad2.y;
        #pragma unroll
        for (int of = 16; of; of >>= 1) {
            ps += __shfl_xor_sync(0xffffffffu, ps, of);
            pd += __shfl_xor_sync(0xffffffffu, pd, of);
        }
        if (lane == 0) { d_s2[v] = ps; d_d2[v] = pd; if (v < NN) d_den2[v] = 0.f; }
    }
}

// ---------------- merged: GAT2 den (det+random) + glb den/numerator ----------------
__global__ __launch_bounds__(256) void k_post2(const int* __restrict__ ei) {
    int b = blockIdx.x, tid = threadIdx.x;
    if (b < NBDEN) {
        int i = b * 256 + tid;
        if (i < NN) {
            int g = i / NPER;
            float d2i = d_d2[i];
            atomicAdd(&d_den2[i], expf(lrelu(d_s2[NN + g] + d2i)) + expf(lrelu(d_s2[i] + d2i)));
        } else if (i < NN + EE) {
            int e = i - NN;
            int s = ei[e], d = ei[EE + e];
            atomicAdd(&d_den2[d], expf(lrelu(d_s2[s] + d_d2[d])));
        }
    } else {
        __shared__ float sred[256];
        __shared__ float sdn[4];
        int gb = b - NBDEN;
        int g = gb / NCHUNK, c = gb % NCHUNK;
        int j = tid & 63, r = tid >> 6;
        float d2g = d_d2[NN + g];
        int i0 = g * NPER + c * CHUNK;
        float acc = 0.f, den = 0.f;
        for (int i = i0 + r; i < i0 + CHUNK; i += 4) {
            float ex = expf(lrelu(d_s2[i] + d2g));
            acc += ex * d_xh2[i * 64 + j];
            den += ex;
        }
        if (c == 0 && r == 0) {
            float exs = expf(lrelu(d_s2[NN + g] + d2g));
            acc += exs * d_xh2[(NN + g) * 64 + j];
            den += exs;
        }
        sred[tid] = acc;
        if (j == 0) sdn[r] = den;
        __syncthreads();
        if (r == 0) {
            acc += sred[tid + 64] + sred[tid + 128] + sred[tid + 192];
            atomicAdd(&d_acc2[g * 64 + j], acc);
            if (j == 0) atomicAdd(&d_den2[NN + g], sdn[0] + sdn[1] + sdn[2] + sdn[3]);
        }
    }
}

// ---------------- merged: emit src/dst + att + tree_glb ----------------
__global__ void k_edgesfin(const int* __restrict__ ei, const float* __restrict__ b2,
                           float* __restrict__ out) {
    int b = blockIdx.x;
    if (b < EBLK) {
        int e = b * 256 + threadIdx.x;
        if (e >= ETOT) return;
        int s, d; edge_sd(e, ei, s, d);
        out[2048 + e] = (float)s;
        out[2048 + ETOT + e] = (float)d;
        float ex = expf(lrelu(d_s2[s] + d_d2[d]));
        out[2048 + 2 * ETOT + e] = ex / (d_den2[d] + 1e-16f);
    } else {
        int t = (b - EBLK) * 256 + threadIdx.x;
        int g = t >> 6, j = t & 63;
        out[t] = d_acc2[t] / (d_den2[NN + g] + 1e-16f) + b2[j];
    }
}

// ---------------- launch ----------------
extern "C" void kernel_launch(void* const* d_in, const int* in_sizes, int n_in,
                              void* d_out, int out_size) {
    const float* tree_feature = (const float*)d_in[0];
    const int*   edge_index   = (const int*)d_in[1];
    const float* ln_tree_g  = (const float*)d_in[4];
    const float* ln_tree_b  = (const float*)d_in[5];
    const float* lin_tree_W = (const float*)d_in[6];
    const float* lin_tree_b = (const float*)d_in[7];
    const float* ln_var_g   = (const float*)d_in[8];
    const float* ln_var_b   = (const float*)d_in[9];
    const float* lin_var_W  = (const float*)d_in[10];
    const float* lin_var_b  = (const float*)d_in[11];
    const float* glb_W      = (const float*)d_in[12];
    const float* glb_b      = (const float*)d_in[13];
    const float* glbNode    = (const float*)d_in[14];
    const float* gat1_W     = (const float*)d_in[15];
    const float* gat1_as    = (const float*)d_in[16];
    const float* gat1_ad    = (const float*)d_in[17];
    const float* gat1_b     = (const float*)d_in[18];
    const float* gat2_W     = (const float*)d_in[19];
    const float* gat2_as    = (const float*)d_in[20];
    const float* gat2_ad    = (const float*)d_in[21];
    const float* gat2_b     = (const float*)d_in[22];
    float* out = (float*)d_out;

    k_preA<<<17, 256>>>(lin_tree_W, lin_tree_b, lin_var_W, lin_var_b, glb_W, glb_b);
    k_preB<<<33, 256>>>(glbNode, gat1_W, gat1_as, gat1_ad);
    k_node1<<<NN / 32, 256>>>(tree_feature, ln_tree_g, ln_tree_b,
                              ln_var_g, ln_var_b, gat1_as, gat1_ad);
    k_e2acc<<<(EE / 2 * 32) / 256, 256>>>(edge_index);
    k_node2<<<NTOT / 32, 256>>>(gat2_W, gat1_b, gat2_as, gat2_ad);
    k_post2<<<NBDEN + BB * NCHUNK, 256>>>(edge_index);
    k_edgesfin<<<EBLK + 8, 256>>>(edge_index, gat2_b, out);
}